// round 12
// baseline (speedup 1.0000x reference)
#include <cuda_runtime.h>
#include <cuda_fp16.h>
#include <math.h>

#define DIMC 1024
#define NTOK 2048
#define BATCHN 2
#define TTOK (BATCHN*NTOK)
#define NHEADS 16
#define HDIM 64
#define DFF 4096

typedef __half hf;
typedef __half2 hf2;

/* ---------------- scratch (device globals; no allocations allowed) -------- */
__device__ float g_sc  [(size_t)BATCHN*NTOK*NTOK];          /* 32 MB kernel-attn scores */
__device__ hf g_whi[16777216];
__device__ hf g_lnhi [(size_t)TTOK*DIMC];
__device__ hf g_qkvhi[(size_t)TTOK*3*DIMC];
__device__ hf g_schi [(size_t)BATCHN*NTOK*NTOK];
__device__ hf g_aohi [(size_t)TTOK*DIMC];
__device__ hf g_reshi[(size_t)TTOK*DIMC];
__device__ hf g_ffhi [(size_t)TTOK*DFF];

#define W_QKV  0LL
#define W_PROJ 3145728LL
#define W_KQ   4194304LL
#define W_KK   5242880LL
#define W_KV   6291456LL
#define W_KO   7340032LL
#define W_FC1  8388608LL
#define W_FC2  12582912LL

/* ---------------- helpers ------------------------------------------------- */
__device__ __forceinline__ float gelu_f(float x) {
    return 0.5f * x * (1.0f + erff(x * 0.7071067811865476f));
}
__device__ __forceinline__ float theta_fn(float x) {
    float sg = 1.0f / (1.0f + __expf(-x));
    float rl = fmaxf(x, 0.0f);
    return 0.5f + 0.2f * sg + 0.15f * tanhf(x) + 0.1f * rl;
}
__device__ __forceinline__ void ldsm4(unsigned& r0, unsigned& r1, unsigned& r2, unsigned& r3, unsigned a) {
    asm volatile("ldmatrix.sync.aligned.m8n8.x4.shared.b16 {%0,%1,%2,%3}, [%4];"
                 : "=r"(r0), "=r"(r1), "=r"(r2), "=r"(r3) : "r"(a));
}
__device__ __forceinline__ void ldsm4t(unsigned& r0, unsigned& r1, unsigned& r2, unsigned& r3, unsigned a) {
    asm volatile("ldmatrix.sync.aligned.m8n8.x4.trans.shared.b16 {%0,%1,%2,%3}, [%4];"
                 : "=r"(r0), "=r"(r1), "=r"(r2), "=r"(r3) : "r"(a));
}
__device__ __forceinline__ void mma16816(float* d, const unsigned* a, const unsigned* b) {
    asm volatile(
        "mma.sync.aligned.m16n8k16.row.col.f32.f16.f16.f32 "
        "{%0,%1,%2,%3}, {%4,%5,%6,%7}, {%8,%9}, {%0,%1,%2,%3};"
        : "+f"(d[0]), "+f"(d[1]), "+f"(d[2]), "+f"(d[3])
        : "r"(a[0]), "r"(a[1]), "r"(a[2]), "r"(a[3]), "r"(b[0]), "r"(b[1]));
}
__device__ __forceinline__ void cpa16(unsigned dst, const void* src) {
    asm volatile("cp.async.cg.shared.global [%0], [%1], 16;" :: "r"(dst), "l"(src));
}
#define CP_COMMIT() asm volatile("cp.async.commit_group;")
#define CP_WAIT1()  asm volatile("cp.async.wait_group 1;")
#define CP_WAIT2()  asm volatile("cp.async.wait_group 2;")

/* ---------------- fp16 tensor-core GEMM (cp.async 3-stage, k-tile 64) -----
   C[z] = alpha * A[z](M x K) * op(B[z]) + bias [+ R] ; op = B (NN) or B^T (TB)
   A, B single RN fp16. OUTM: 0 = fp32 C, 1 = fp16 Chi (+fp32 C if RESID).
   RESID: adds fp32 R (same layout as C) in epilogue.
   M%128==0, N%256==0 (NTILE=256), K%64==0.                                 */
template<int NTILE, bool TB, bool GELU, int OUTM, bool RESID>
__global__ void __launch_bounds__(256, 1) bgemm(
    const hf* __restrict__ Ahi, const hf* __restrict__ Bhi,
    float* __restrict__ C, hf* __restrict__ Chi,
    const float* __restrict__ R, const float* __restrict__ bias,
    int K, int lda, int ldb, int ldc, int zdiv,
    long long sA1, long long sA2, long long sB1, long long sB2,
    long long sC1, long long sC2, float alpha)
{
    extern __shared__ char dsm[];
    constexpr int KT     = 64;
    constexpr int ABYTES = 16384;            /* 128 rows x 128B */
    constexpr int BBYTES = NTILE * 128;      /* TB: NTILE rows x 128B ; NN: 64 rows x NTILE*2 */
    constexpr int STAGE  = ABYTES + BBYTES;

    unsigned smRaw  = (unsigned)__cvta_generic_to_shared(dsm);
    unsigned smBase = (smRaw + 1023u) & ~1023u;

    int z = blockIdx.z, z1 = z / zdiv, z2 = z % zdiv;
    const hf* Ah = Ahi + z1 * sA1 + z2 * sA2;
    const hf* Bh = Bhi + z1 * sB1 + z2 * sB2;
    long long coff = z1 * sC1 + z2 * sC2;

    int rowBase = blockIdx.y * 128;
    int colBase = blockIdx.x * NTILE;
    int tid = threadIdx.x, lane = tid & 31, w = tid >> 5;

    constexpr int MF = 4;                 /* warp tile 64 x (NTILE/4) */
    constexpr int NF = NTILE / 32;        /* 8 */
    int warpRow = (w & 1) * 64;
    int warpCol = (w >> 1) * (NTILE / 4);

    float acc[MF][NF][4] = {};

    auto issue = [&](int s, int k0) {
        unsigned sA = smBase + s * STAGE;
        unsigned sB = sA + ABYTES;
        #pragma unroll
        for (int i = 0; i < 4; i++) {
            int li = tid + i * 256, r = li >> 3, ch = li & 7;
            const hf* src = Ah + (long long)(rowBase + r) * lda + k0 + ch * 8;
            cpa16(sA + r * 128 + ((ch ^ (r & 7)) << 4), src);
        }
        if (TB) {
            #pragma unroll
            for (int i = 0; i < NTILE / 32; i++) {
                int li = tid + i * 256, r = li >> 3, ch = li & 7;
                const hf* src = Bh + (long long)(colBase + r) * ldb + k0 + ch * 8;
                cpa16(sB + r * 128 + ((ch ^ (r & 7)) << 4), src);
            }
        } else {
            constexpr int CPR = NTILE / 8;            /* 16B chunks per B row */
            #pragma unroll
            for (int i = 0; i < (64 * CPR) / 256; i++) {
                int li = tid + i * 256;
                int r = li / CPR, ch = li % CPR;
                const hf* src = Bh + (long long)(k0 + r) * ldb + colBase + ch * 8;
                cpa16(sB + r * (NTILE * 2) + ((ch ^ (r & 7)) << 4), src);
            }
        }
    };

    auto compute = [&](int s) {
        unsigned sA = smBase + s * STAGE;
        unsigned sB = sA + ABYTES;
        #pragma unroll
        for (int ks = 0; ks < 4; ks++) {
            unsigned ah[MF][4];
            #pragma unroll
            for (int mf = 0; mf < MF; mf++) {
                int ar = warpRow + mf * 16 + (lane & 15);
                int ac = ks * 2 + (lane >> 4);
                ldsm4(ah[mf][0], ah[mf][1], ah[mf][2], ah[mf][3],
                      sA + ar * 128 + ((ac ^ (ar & 7)) << 4));
            }
            #pragma unroll
            for (int np = 0; np < NF / 2; np++) {
                unsigned bh[2][2];
                if (!TB) {
                    int bk = ks * 16 + (lane & 15);
                    int nc = (warpCol + np * 16 + ((lane >> 4) << 3)) >> 3;
                    ldsm4t(bh[0][0], bh[0][1], bh[1][0], bh[1][1],
                           sB + bk * (NTILE * 2) + ((nc ^ (bk & 7)) << 4));
                } else {
                    int br = warpCol + np * 16 + ((lane >> 4) << 3) + (lane & 7);
                    int kc = ks * 2 + ((lane >> 3) & 1);
                    ldsm4(bh[0][0], bh[0][1], bh[1][0], bh[1][1],
                          sB + br * 128 + ((kc ^ (br & 7)) << 4));
                }
                #pragma unroll
                for (int mf = 0; mf < MF; mf++)
                    #pragma unroll
                    for (int j = 0; j < 2; j++) mma16816(acc[mf][2*np+j], ah[mf], bh[j]);
            }
        }
    };

    int nk = K / KT;
    issue(0, 0); CP_COMMIT();
    if (nk > 1) issue(1, KT);
    CP_COMMIT();
    for (int i = 0; i < nk; i++) {
        CP_WAIT1();
        __syncthreads();
        if (i + 2 < nk) issue((i + 2) % 3, (i + 2) * KT);
        CP_COMMIT();
        compute(i % 3);
    }

    #pragma unroll
    for (int mf = 0; mf < MF; mf++) {
        #pragma unroll
        for (int nf = 0; nf < NF; nf++) {
            int row = rowBase + warpRow + mf * 16 + (lane >> 2);
            int col = colBase + warpCol + nf * 8 + (lane & 3) * 2;
            float bx = 0.f, by = 0.f;
            if (bias) { float2 bb = *(const float2*)(bias + col); bx = bb.x; by = bb.y; }
            long long o0 = coff + (long long)row * ldc + col;
            long long o1 = coff + (long long)(row + 8) * ldc + col;
            float v0 = acc[mf][nf][0] * alpha + bx;
            float v1 = acc[mf][nf][1] * alpha + by;
            float v2 = acc[mf][nf][2] * alpha + bx;
            float v3 = acc[mf][nf][3] * alpha + by;
            if (GELU) { v0 = gelu_f(v0); v1 = gelu_f(v1); v2 = gelu_f(v2); v3 = gelu_f(v3); }
            if (RESID) {
                float2 r0 = *(const float2*)(R + o0);
                float2 r1 = *(const float2*)(R + o1);
                v0 += r0.x; v1 += r0.y; v2 += r1.x; v3 += r1.y;
            }
            if (OUTM == 0 || RESID) {
                *(float2*)(C + o0) = make_float2(v0, v1);
                *(float2*)(C + o1) = make_float2(v2, v3);
            }
            if (OUTM == 1) {
                *(hf2*)(Chi + o0) = __floats2half2_rn(v0, v1);
                *(hf2*)(Chi + o1) = __floats2half2_rn(v2, v3);
            }
        }
    }
}

/* ---------------- fused flash MHA (QK^T + softmax + PV), all single fp16 -- */
__global__ void __launch_bounds__(256, 1) flash_mha(
    const hf* __restrict__ QKVhi, hf* __restrict__ Ohi)
{
    extern __shared__ char dsm[];
    unsigned smRaw = (unsigned)__cvta_generic_to_shared(dsm);
    unsigned smQ  = (smRaw + 1023u) & ~1023u;    /* 16K */
    unsigned smKV = smQ + 16384;                 /* 3 stages x [KH 16K | VH 16K] */

    int bh = blockIdx.y;
    int b = bh >> 4, h = bh & 15;
    long long rowBase = (long long)b * NTOK;
    int qRow0 = blockIdx.x * 128;
    const int ld = 3 * DIMC;
    int qcol = h * 64, kcol = DIMC + h * 64, vcol = 2 * DIMC + h * 64;

    int tid = threadIdx.x, lane = tid & 31, w = tid >> 5;

    #pragma unroll
    for (int i = 0; i < 4; i++) {
        int li = tid + i * 256, r = li >> 3, ch = li & 7;
        unsigned sw = r * 128 + ((ch ^ (r & 7)) << 4);
        cpa16(smQ + sw, QKVhi + (rowBase + qRow0 + r) * ld + qcol + ch * 8);
    }
    CP_COMMIT();

    auto issueKV = [&](int s, int kt0) {
        unsigned base = smKV + s * 32768;
        #pragma unroll
        for (int i = 0; i < 4; i++) {
            int li = tid + i * 256, r = li >> 3, ch = li & 7;
            unsigned sw = r * 128 + ((ch ^ (r & 7)) << 4);
            long long g = (rowBase + kt0 + r) * ld;
            cpa16(base + sw,         QKVhi + g + kcol + ch * 8);
            cpa16(base + 16384 + sw, QKVhi + g + vcol + ch * 8);
        }
    };

    issueKV(0, 0);   CP_COMMIT();
    issueKV(1, 128); CP_COMMIT();

    CP_WAIT2();
    __syncthreads();

    unsigned qh[4][4];
    {
        int ar = w * 16 + (lane & 15);
        hf2 s2 = __floats2half2_rn(0.125f, 0.125f);
        #pragma unroll
        for (int c = 0; c < 4; c++) {
            int ac = c * 2 + (lane >> 4);
            ldsm4(qh[c][0], qh[c][1], qh[c][2], qh[c][3],
                  smQ + ar * 128 + ((ac ^ (ar & 7)) << 4));
            #pragma unroll
            for (int r = 0; r < 4; r++) {
                hf2 t = *(hf2*)&qh[c][r]; t = __hmul2(t, s2); qh[c][r] = *(unsigned*)&t;
            }
        }
    }

    float o[8][4] = {};
    float l0 = 0.f, l1 = 0.f;

    for (int kt = 0; kt < 16; kt++) {
        CP_WAIT1();
        __syncthreads();
        if (kt + 2 < 16) issueKV((kt + 2) % 3, (kt + 2) * 128);
        CP_COMMIT();

        unsigned base = smKV + (kt % 3) * 32768;

        float sacc[16][4] = {};
        #pragma unroll
        for (int c = 0; c < 4; c++) {
            #pragma unroll
            for (int np = 0; np < 8; np++) {
                unsigned kh2[2][2];
                int br = np * 16 + ((lane >> 4) << 3) + (lane & 7);
                int kc = c * 2 + ((lane >> 3) & 1);
                ldsm4(kh2[0][0], kh2[0][1], kh2[1][0], kh2[1][1],
                      base + br * 128 + ((kc ^ (br & 7)) << 4));
                #pragma unroll
                for (int j = 0; j < 2; j++) mma16816(sacc[2*np+j], qh[c], kh2[j]);
            }
        }

        unsigned ph[8][4];
        #pragma unroll
        for (int f = 0; f < 16; f++) {
            float p0 = __expf(sacc[f][0]);
            float p1 = __expf(sacc[f][1]);
            float p2 = __expf(sacc[f][2]);
            float p3 = __expf(sacc[f][3]);
            l0 += p0 + p1;
            l1 += p2 + p3;
            int j = f >> 1, hfi = f & 1;
            hf2 a = __floats2half2_rn(p0, p1);
            hf2 c = __floats2half2_rn(p2, p3);
            ph[j][hfi*2+0] = *(unsigned*)&a;
            ph[j][hfi*2+1] = *(unsigned*)&c;
        }

        unsigned vb = base + 16384;
        #pragma unroll
        for (int j = 0; j < 8; j++) {
            #pragma unroll
            for (int np2 = 0; np2 < 4; np2++) {
                unsigned vh[2][2];
                int bk = j * 16 + (lane & 15);
                int nc = (np2 * 16 + ((lane >> 4) << 3)) >> 3;
                ldsm4t(vh[0][0], vh[0][1], vh[1][0], vh[1][1],
                       vb + bk * 128 + ((nc ^ (bk & 7)) << 4));
                #pragma unroll
                for (int t = 0; t < 2; t++) mma16816(o[2*np2+t], ph[j], vh[t]);
            }
        }
    }

    l0 += __shfl_xor_sync(0xffffffffu, l0, 1);
    l0 += __shfl_xor_sync(0xffffffffu, l0, 2);
    l1 += __shfl_xor_sync(0xffffffffu, l1, 1);
    l1 += __shfl_xor_sync(0xffffffffu, l1, 2);
    float i0 = 1.0f / l0, i1 = 1.0f / l1;

    long long or0 = (rowBase + qRow0 + w * 16 + (lane >> 2)) * DIMC + h * 64;
    #pragma unroll
    for (int nf = 0; nf < 8; nf++) {
        int col = nf * 8 + (lane & 3) * 2;
        *(hf2*)(Ohi + or0 + col)            = __floats2half2_rn(o[nf][0] * i0, o[nf][1] * i0);
        *(hf2*)(Ohi + or0 + 8 * DIMC + col) = __floats2half2_rn(o[nf][2] * i1, o[nf][3] * i1);
    }
}

/* ---------------- fp32 -> fp16 convert (weights) --------------------------- */
__global__ void __launch_bounds__(256) conv_vec(
    const float* __restrict__ in, hf* __restrict__ hi)
{
    long long i = ((long long)blockIdx.x * 256 + threadIdx.x) * 4;
    float4 v = *(const float4*)(in + i);
    *(hf2*)(hi + i)     = __floats2half2_rn(v.x, v.y);
    *(hf2*)(hi + i + 2) = __floats2half2_rn(v.z, v.w);
}

/* ---------------- theta + softmax -> fp16 ---------------------------------- */
__global__ void __launch_bounds__(256) theta_softmax2048_hf(
    const float* __restrict__ S, hf* __restrict__ Phi)
{
    __shared__ float red[8];
    const float* row = S + (long long)blockIdx.x * 2048;
    long long ob = (long long)blockIdx.x * 2048;
    int tid = threadIdx.x;
    float4 v0 = ((const float4*)row)[tid];
    float4 v1 = ((const float4*)row)[tid + 256];
    v0.x = theta_fn(v0.x); v0.y = theta_fn(v0.y); v0.z = theta_fn(v0.z); v0.w = theta_fn(v0.w);
    v1.x = theta_fn(v1.x); v1.y = theta_fn(v1.y); v1.z = theta_fn(v1.z); v1.w = theta_fn(v1.w);
    float m = fmaxf(fmaxf(fmaxf(v0.x, v0.y), fmaxf(v0.z, v0.w)),
                    fmaxf(fmaxf(v1.x, v1.y), fmaxf(v1.z, v1.w)));
    #pragma unroll
    for (int o = 16; o; o >>= 1) m = fmaxf(m, __shfl_xor_sync(0xffffffffu, m, o));
    if ((tid & 31) == 0) red[tid >> 5] = m;
    __syncthreads();
    m = fmaxf(fmaxf(fmaxf(red[0], red[1]), fmaxf(red[2], red[3])),
              fmaxf(fmaxf(red[4], red[5]), fmaxf(red[6], red[7])));
    v0.x = __expf(v0.x - m); v0.y = __expf(v0.y - m); v0.z = __expf(v0.z - m); v0.w = __expf(v0.w - m);
    v1.x = __expf(v1.x - m); v1.y = __expf(v1.y - m); v1.z = __expf(v1.z - m); v1.w = __expf(v1.w - m);
    float s = v0.x + v0.y + v0.z + v0.w + v1.x + v1.y + v1.z + v1.w;
    #pragma unroll
    for (int o = 16; o; o >>= 1) s += __shfl_xor_sync(0xffffffffu, s, o);
    __syncthreads();
    if ((tid & 31) == 0) red[tid >> 5] = s;
    __syncthreads();
    s = red[0] + red[1] + red[2] + red[3] + red[4] + red[5] + red[6] + red[7];
    float r = 1.0f / s;
    v0.x *= r; v0.y *= r; v0.z *= r; v0.w *= r;
    v1.x *= r; v1.y *= r; v1.z *= r; v1.w *= r;
    *(hf2*)(Phi + ob + tid*4)            = __floats2half2_rn(v0.x, v0.y);
    *(hf2*)(Phi + ob + tid*4 + 2)        = __floats2half2_rn(v0.z, v0.w);
    *(hf2*)(Phi + ob + 1024 + tid*4)     = __floats2half2_rn(v1.x, v1.y);
    *(hf2*)(Phi + ob + 1024 + tid*4 + 2) = __floats2half2_rn(v1.z, v1.w);
}

/* ---------------- LayerNorm over 1024 -> fp16 ----------------------------- */
__global__ void __launch_bounds__(256) layernorm1024_hf(
    const float* __restrict__ X, const float* __restrict__ g,
    const float* __restrict__ bta, hf* __restrict__ Yhi)
{
    __shared__ float rs[8], rq[8];
    long long base = (long long)blockIdx.x * 1024;
    int tid = threadIdx.x;
    float4 v = *(const float4*)(X + base + tid * 4);
    float s = v.x + v.y + v.z + v.w;
    float q = v.x*v.x + v.y*v.y + v.z*v.z + v.w*v.w;
    #pragma unroll
    for (int o = 16; o; o >>= 1) {
        s += __shfl_xor_sync(0xffffffffu, s, o);
        q += __shfl_xor_sync(0xffffffffu, q, o);
    }
    if ((tid & 31) == 0) { rs[tid >> 5] = s; rq[tid >> 5] = q; }
    __syncthreads();
    s = rs[0] + rs[1] + rs[2] + rs[3] + rs[4] + rs[5] + rs[6] + rs[7];
    q = rq[0] + rq[1] + rq[2] + rq[3] + rq[4] + rq[5] + rq[6] + rq[7];
    float mu  = s * (1.0f / 1024.0f);
    float var = q * (1.0f / 1024.0f) - mu * mu;
    float inv = rsqrtf(var + 1e-5f);
    float4 gg = *(const float4*)(g + tid * 4);
    float4 bb = *(const float4*)(bta + tid * 4);
    float o0 = (v.x - mu) * inv * gg.x + bb.x;
    float o1 = (v.y - mu) * inv * gg.y + bb.y;
    float o2 = (v.z - mu) * inv * gg.z + bb.z;
    float o3 = (v.w - mu) * inv * gg.w + bb.w;
    *(hf2*)(Yhi + base + tid*4)     = __floats2half2_rn(o0, o1);
    *(hf2*)(Yhi + base + tid*4 + 2) = __floats2half2_rn(o2, o3);
}

/* ---------------- fp32 -> fp16 (residual stream snapshot) ------------------ */
__global__ void __launch_bounds__(256) snap_hf(
    const float* __restrict__ in, hf* __restrict__ hi)
{
    long long i = ((long long)blockIdx.x * 256 + threadIdx.x) * 4;
    float4 v = *(const float4*)(in + i);
    *(hf2*)(hi + i)     = __floats2half2_rn(v.x, v.y);
    *(hf2*)(hi + i + 2) = __floats2half2_rn(v.z, v.w);
}

/* ---------------- host-side dispatch -------------------------------------- */
#define SMEM_G     148480   /* 3*(16384+32768) + 1024 */
#define SMEM_FLASH 115712   /* 16384 + 3*32768 + 1024 */

extern "C" void kernel_launch(void* const* d_in, const int* in_sizes, int n_in,
                              void* d_out, int out_size)
{
    const float* x     = (const float*)d_in[0];
    const float* ln1_g = (const float*)d_in[1];
    const float* ln1_b = (const float*)d_in[2];
    const float* qkv_w = (const float*)d_in[3];
    const float* qkv_b = (const float*)d_in[4];
    const float* proj_w= (const float*)d_in[5];
    const float* proj_b= (const float*)d_in[6];
    const float* kq_w  = (const float*)d_in[7];
    const float* kq_b  = (const float*)d_in[8];
    const float* kk_w  = (const float*)d_in[9];
    const float* kk_b  = (const float*)d_in[10];
    const float* kv_w  = (const float*)d_in[11];
    const float* kv_b  = (const float*)d_in[12];
    const float* ko_w  = (const float*)d_in[13];
    const float* ko_b  = (const float*)d_in[14];
    const float* ln2_g = (const float*)d_in[15];
    const float* ln2_b = (const float*)d_in[16];
    const float* fc1_w = (const float*)d_in[17];
    const float* fc1_b = (const float*)d_in[18];
    const float* fc2_w = (const float*)d_in[19];
    const float* fc2_b = (const float*)d_in[20];
    float* out = (float*)d_out;

    float *sc;
    hf *whi, *lnhi, *qkvhi, *schi, *aohi, *reshi, *ffhi;
    cudaGetSymbolAddress((void**)&sc,    g_sc);
    cudaGetSymbolAddress((void**)&whi,   g_whi);
    cudaGetSymbolAddress((void**)&lnhi,  g_lnhi);
    cudaGetSymbolAddress((void**)&qkvhi, g_qkvhi);
    cudaGetSymbolAddress((void**)&schi,  g_schi);
    cudaGetSymbolAddress((void**)&aohi,  g_aohi);
    cudaGetSymbolAddress((void**)&reshi, g_reshi);
    cudaGetSymbolAddress((void**)&ffhi,  g_ffhi);

    cudaFuncSetAttribute(bgemm<256, false, false, 1, false>, cudaFuncAttributeMaxDynamicSharedMemorySize, SMEM_G);
    cudaFuncSetAttribute(bgemm<256, false, true,  1, false>, cudaFuncAttributeMaxDynamicSharedMemorySize, SMEM_G);
    cudaFuncSetAttribute(bgemm<256, false, false, 1, true >, cudaFuncAttributeMaxDynamicSharedMemorySize, SMEM_G);
    cudaFuncSetAttribute(bgemm<256, false, false, 0, true >, cudaFuncAttributeMaxDynamicSharedMemorySize, SMEM_G);
    cudaFuncSetAttribute(bgemm<256, true,  false, 0, false>, cudaFuncAttributeMaxDynamicSharedMemorySize, SMEM_G);
    cudaFuncSetAttribute(flash_mha, cudaFuncAttributeMaxDynamicSharedMemorySize, SMEM_FLASH);

    const long long NN = (long long)NTOK * NTOK;
    const long long TC = (long long)NTOK * DIMC;
    dim3 tb(256);

    /* launches 1-5 (launch #6 = QKV GEMM for ncu -s 5 -c 1) */
    conv_vec<<<3072, tb>>>(qkv_w,  whi + W_QKV);
    conv_vec<<<1024, tb>>>(proj_w, whi + W_PROJ);
    conv_vec<<<1024, tb>>>(kq_w,   whi + W_KQ);
    conv_vec<<<1024, tb>>>(kk_w,   whi + W_KK);
    layernorm1024_hf<<<TTOK, tb>>>(x, ln1_g, ln1_b, lnhi);

    /* launch #6: qkv = ln1 @ qkv_w + b */
    bgemm<256, false, false, 1, false><<<dim3(12, 32, 1), tb, SMEM_G>>>(
        lnhi, whi + W_QKV, nullptr, qkvhi, nullptr, qkv_b,
        1024, 1024, 3072, 3072, 1, 0,0, 0,0, 0,0, 1.0f);

    conv_vec<<<1024, tb>>>(kv_w,   whi + W_KV);
    conv_vec<<<1024, tb>>>(ko_w,   whi + W_KO);
    conv_vec<<<4096, tb>>>(fc1_w,  whi + W_FC1);
    conv_vec<<<4096, tb>>>(fc2_w,  whi + W_FC2);

    /* fused MHA attention -> aohi */
    flash_mha<<<dim3(16, 32), tb, SMEM_FLASH>>>(qkvhi, aohi);

    /* proj: out = x + ao @ proj_w + b ; also snapshot reshi fp16 */
    bgemm<256, false, false, 1, true><<<dim3(4, 32, 1), tb, SMEM_G>>>(
        aohi, whi + W_PROJ, out, reshi, x, proj_b,
        1024, 1024, 1024, 1024, 1, 0,0, 0,0, 0,0, 1.0f);

    /* ---- sublayer 2: kernel attention ---- */
    hf* bqhi = qkvhi;
    hf* bkhi = qkvhi + (size_t)TTOK*DIMC;
    hf* bvhi = qkvhi + (size_t)2*TTOK*DIMC;

    bgemm<256, false, false, 1, false><<<dim3(4, 32, 1), tb, SMEM_G>>>(
        reshi, whi + W_KQ, nullptr, bqhi, nullptr, kq_b,
        1024, 1024, 1024, 1024, 1, 0,0, 0,0, 0,0, 1.0f);
    bgemm<256, false, false, 1, false><<<dim3(4, 32, 1), tb, SMEM_G>>>(
        reshi, whi + W_KK, nullptr, bkhi, nullptr, kk_b,
        1024, 1024, 1024, 1024, 1, 0,0, 0,0, 0,0, 1.0f);
    bgemm<256, false, false, 1, false><<<dim3(4, 32, 1), tb, SMEM_G>>>(
        reshi, whi + W_KV, nullptr, bvhi, nullptr, kv_b,
        1024, 1024, 1024, 1024, 1, 0,0, 0,0, 0,0, 1.0f);

    /* qk = q @ k^T per batch */
    bgemm<256, true, false, 0, false><<<dim3(8, 16, BATCHN), tb, SMEM_G>>>(
        bqhi, bkhi, sc, nullptr, nullptr, nullptr,
        1024, 1024, 1024, NTOK, 1, TC, 0, TC, 0, NN, 0, 1.0f);

    theta_softmax2048_hf<<<BATCHN*NTOK, tb>>>(sc, schi);

    /* av = attn @ v per batch */
    bgemm<256, false, false, 1, false><<<dim3(4, 16, BATCHN), tb, SMEM_G>>>(
        schi, bvhi, nullptr, aohi, nullptr, nullptr,
        NTOK, NTOK, DIMC, DIMC, 1, NN, 0, TC, 0, TC, 0, 1.0f);

    /* ko: out += av @ ko_w + b (in-place residual) */
    bgemm<256, false, false, 0, true><<<dim3(4, 32, 1), tb, SMEM_G>>>(
        aohi, whi + W_KO, out, nullptr, out, ko_b,
        1024, 1024, 1024, 1024, 1, 0,0, 0,0, 0,0, 1.0f);

    /* ---- sublayer 3: FFN ---- */
    layernorm1024_hf<<<TTOK, tb>>>(out, ln2_g, ln2_b, lnhi);
    bgemm<256, false, true, 1, false><<<dim3(16, 32, 1), tb, SMEM_G>>>(
        lnhi, whi + W_FC1, nullptr, ffhi, nullptr, fc1_b,
        1024, 1024, 4096, 4096, 1, 0,0, 0,0, 0,0, 1.0f);
    bgemm<256, false, false, 0, true><<<dim3(4, 32, 1), tb, SMEM_G>>>(
        ffhi, whi + W_FC2, out, nullptr, out, fc2_b,
        4096, 4096, 1024, 1024, 1, 0,0, 0,0, 0,0, 1.0f);
}

// round 13
// speedup vs baseline: 1.3381x; 1.3381x over previous
#include <cuda_runtime.h>
#include <cuda_fp16.h>
#include <math.h>

#define DIMC 1024
#define NTOK 2048
#define BATCHN 2
#define TTOK (BATCHN*NTOK)
#define NHEADS 16
#define HDIM 64
#define DFF 4096

typedef __half hf;
typedef __half2 hf2;

/* ---------------- scratch (device globals; no allocations allowed) -------- */
__device__ float g_sc  [(size_t)BATCHN*NTOK*NTOK];          /* 32 MB kernel-attn scores */
__device__ float g_bufA[(size_t)TTOK*DIMC];                 /* 16 MB fp32 */
__device__ hf g_whi[16777216];
__device__ hf g_lnhi [(size_t)TTOK*DIMC];
__device__ hf g_qkvhi[(size_t)TTOK*3*DIMC],    g_qkvlo[(size_t)TTOK*3*DIMC];
__device__ hf g_schi [(size_t)BATCHN*NTOK*NTOK];
__device__ hf g_sclo [(size_t)BATCHN*NTOK*NTOK];
__device__ hf g_aohi [(size_t)TTOK*DIMC];
__device__ hf g_reshi[(size_t)TTOK*DIMC];
__device__ hf g_ffhi [(size_t)TTOK*DFF];

#define W_QKV  0LL
#define W_PROJ 3145728LL
#define W_KQ   4194304LL
#define W_KK   5242880LL
#define W_KV   6291456LL
#define W_KO   7340032LL
#define W_FC1  8388608LL
#define W_FC2  12582912LL

/* ---------------- helpers ------------------------------------------------- */
__device__ __forceinline__ float gelu_f(float x) {
    return 0.5f * x * (1.0f + erff(x * 0.7071067811865476f));
}
__device__ __forceinline__ float theta_fn(float x) {
    float sg = 1.0f / (1.0f + __expf(-x));
    float rl = fmaxf(x, 0.0f);
    return 0.5f + 0.2f * sg + 0.15f * tanhf(x) + 0.1f * rl;
}
__device__ __forceinline__ void split_pair(float x, float y, hf2& h, hf2& l) {
    h = __floats2half2_rn(x, y);
    l = __floats2half2_rn(x - __low2float(h), y - __high2float(h));
}
__device__ __forceinline__ void ldsm4(unsigned& r0, unsigned& r1, unsigned& r2, unsigned& r3, unsigned a) {
    asm volatile("ldmatrix.sync.aligned.m8n8.x4.shared.b16 {%0,%1,%2,%3}, [%4];"
                 : "=r"(r0), "=r"(r1), "=r"(r2), "=r"(r3) : "r"(a));
}
__device__ __forceinline__ void ldsm4t(unsigned& r0, unsigned& r1, unsigned& r2, unsigned& r3, unsigned a) {
    asm volatile("ldmatrix.sync.aligned.m8n8.x4.trans.shared.b16 {%0,%1,%2,%3}, [%4];"
                 : "=r"(r0), "=r"(r1), "=r"(r2), "=r"(r3) : "r"(a));
}
__device__ __forceinline__ void mma16816(float* d, const unsigned* a, const unsigned* b) {
    asm volatile(
        "mma.sync.aligned.m16n8k16.row.col.f32.f16.f16.f32 "
        "{%0,%1,%2,%3}, {%4,%5,%6,%7}, {%8,%9}, {%0,%1,%2,%3};"
        : "+f"(d[0]), "+f"(d[1]), "+f"(d[2]), "+f"(d[3])
        : "r"(a[0]), "r"(a[1]), "r"(a[2]), "r"(a[3]), "r"(b[0]), "r"(b[1]));
}
__device__ __forceinline__ void cpa16(unsigned dst, const void* src) {
    asm volatile("cp.async.cg.shared.global [%0], [%1], 16;" :: "r"(dst), "l"(src));
}
#define CP_COMMIT() asm volatile("cp.async.commit_group;")
#define CP_WAIT1()  asm volatile("cp.async.wait_group 1;")
#define CP_WAIT2()  asm volatile("cp.async.wait_group 2;")

/* ---------------- fp16 tensor-core GEMM (cp.async 3-stage) ----------------
   C[z] = alpha * A[z](M x K) * op(B[z]) + bias ; op = B [K,N] (NN) or B^T (TB)
   ASPLIT: A fp16 hi/lo (2 MMAs), k-tile 32.
   !ASPLIT (NN only): A single fp16, k-tile 64 (1 MMA).
   OUTM: 0 = fp32 C, 1 = fp16 hi, 2 = fp16 hi+lo.
   M%128==0, N%256==0 (NTILE=256).                                          */
template<int NTILE, bool TB, bool ASPLIT, bool GELU, int OUTM>
__global__ void __launch_bounds__(256, 1) bgemm(
    const hf* __restrict__ Ahi, const hf* __restrict__ Alo,
    const hf* __restrict__ Bhi,
    float* __restrict__ C, hf* __restrict__ Chi, hf* __restrict__ Clo,
    const float* __restrict__ bias,
    int K, int lda, int ldb, int ldc, int zdiv,
    long long sA1, long long sA2, long long sB1, long long sB2,
    long long sC1, long long sC2, float alpha)
{
    extern __shared__ char dsm[];
    constexpr int KT     = ASPLIT ? 32 : 64;
    constexpr int KS     = KT / 16;
    constexpr int ABYTES = 16384;   /* 128 rows x 128B: ASPLIT hi|lo over k32, single hi over k64 */
    constexpr int BBYTES = TB ? NTILE * 128 : (ASPLIT ? NTILE * 64 : NTILE * 128);
    constexpr int STAGE  = ABYTES + BBYTES;

    unsigned smRaw  = (unsigned)__cvta_generic_to_shared(dsm);
    unsigned smBase = (smRaw + 1023u) & ~1023u;

    int z = blockIdx.z, z1 = z / zdiv, z2 = z % zdiv;
    const hf* Ah = Ahi + z1 * sA1 + z2 * sA2;
    const hf* Al = ASPLIT ? (Alo + z1 * sA1 + z2 * sA2) : nullptr;
    const hf* Bh = Bhi + z1 * sB1 + z2 * sB2;
    long long coff = z1 * sC1 + z2 * sC2;

    int rowBase = blockIdx.y * 128;
    int colBase = blockIdx.x * NTILE;
    int tid = threadIdx.x, lane = tid & 31, w = tid >> 5;

    constexpr int MF = 4;                 /* warp tile 64 x (NTILE/4) */
    constexpr int NF = NTILE / 32;        /* 8 */
    int warpRow = (w & 1) * 64;
    int warpCol = (w >> 1) * (NTILE / 4);

    float acc[MF][NF][4] = {};

    auto issue = [&](int s, int k0) {
        unsigned sA = smBase + s * STAGE;
        unsigned sB = sA + ABYTES;
        #pragma unroll
        for (int i = 0; i < 4; i++) {
            int li = tid + i * 256, r = li >> 3, ch = li & 7;
            const hf* src;
            if (ASPLIT)
                src = (ch < 4 ? Ah : Al) + (long long)(rowBase + r) * lda + k0 + (ch & 3) * 8;
            else
                src = Ah + (long long)(rowBase + r) * lda + k0 + ch * 8;
            cpa16(sA + r * 128 + ((ch ^ (r & 7)) << 4), src);
        }
        if (TB) {
            #pragma unroll
            for (int i = 0; i < NTILE / 64; i++) {
                int li = tid + i * 256, r = li >> 2, ch = li & 3;
                const hf* src = Bh + (long long)(colBase + r) * ldb + k0 + ch * 8;
                cpa16(sB + r * 128 + ((ch ^ (r & 7)) << 4), src);
            }
        } else {
            constexpr int CPR = NTILE / 8;            /* 16B chunks per B row */
            constexpr int NB  = (KT * CPR) / 256;
            #pragma unroll
            for (int i = 0; i < NB; i++) {
                int li = tid + i * 256;
                int r = li / CPR, ch = li % CPR;
                const hf* src = Bh + (long long)(k0 + r) * ldb + colBase + ch * 8;
                cpa16(sB + r * (NTILE * 2) + ((ch ^ (r & 7)) << 4), src);
            }
        }
    };

    auto compute = [&](int s) {
        unsigned sA = smBase + s * STAGE;
        unsigned sB = sA + ABYTES;
        #pragma unroll
        for (int ks = 0; ks < KS; ks++) {
            unsigned ah[MF][4], al[MF][4];
            #pragma unroll
            for (int mf = 0; mf < MF; mf++) {
                int ar = warpRow + mf * 16 + (lane & 15);
                int ac = ks * 2 + (lane >> 4);
                ldsm4(ah[mf][0], ah[mf][1], ah[mf][2], ah[mf][3],
                      sA + ar * 128 + ((ac ^ (ar & 7)) << 4));
                if (ASPLIT)
                    ldsm4(al[mf][0], al[mf][1], al[mf][2], al[mf][3],
                          sA + ar * 128 + (((ac + 4) ^ (ar & 7)) << 4));
            }
            #pragma unroll
            for (int np = 0; np < NF / 2; np++) {
                unsigned bh[2][2];
                if (!TB) {
                    int bk = ks * 16 + (lane & 15);
                    int nc = (warpCol + np * 16 + ((lane >> 4) << 3)) >> 3;
                    ldsm4t(bh[0][0], bh[0][1], bh[1][0], bh[1][1],
                           sB + bk * (NTILE * 2) + ((nc ^ (bk & 7)) << 4));
                } else {
                    int br = warpCol + np * 16 + ((lane >> 4) << 3) + (lane & 7);
                    int kc = ks * 2 + ((lane >> 3) & 1);
                    ldsm4(bh[0][0], bh[0][1], bh[1][0], bh[1][1],
                          sB + br * 128 + ((kc ^ (br & 7)) << 4));
                }
                #pragma unroll
                for (int mf = 0; mf < MF; mf++)
                    #pragma unroll
                    for (int j = 0; j < 2; j++) mma16816(acc[mf][2*np+j], ah[mf], bh[j]);
                if (ASPLIT) {
                    #pragma unroll
                    for (int mf = 0; mf < MF; mf++)
                        #pragma unroll
                        for (int j = 0; j < 2; j++) mma16816(acc[mf][2*np+j], al[mf], bh[j]);
                }
            }
        }
    };

    int nk = K / KT;
    issue(0, 0); CP_COMMIT();
    if (nk > 1) issue(1, KT);
    CP_COMMIT();
    for (int i = 0; i < nk; i++) {
        CP_WAIT1();
        __syncthreads();
        if (i + 2 < nk) issue((i + 2) % 3, (i + 2) * KT);
        CP_COMMIT();
        compute(i % 3);
    }

    #pragma unroll
    for (int mf = 0; mf < MF; mf++) {
        #pragma unroll
        for (int nf = 0; nf < NF; nf++) {
            int row = rowBase + warpRow + mf * 16 + (lane >> 2);
            int col = colBase + warpCol + nf * 8 + (lane & 3) * 2;
            float bx = 0.f, by = 0.f;
            if (bias) { float2 bb = *(const float2*)(bias + col); bx = bb.x; by = bb.y; }
            float v0 = acc[mf][nf][0] * alpha + bx;
            float v1 = acc[mf][nf][1] * alpha + by;
            float v2 = acc[mf][nf][2] * alpha + bx;
            float v3 = acc[mf][nf][3] * alpha + by;
            if (GELU) { v0 = gelu_f(v0); v1 = gelu_f(v1); v2 = gelu_f(v2); v3 = gelu_f(v3); }
            long long o0 = coff + (long long)row * ldc + col;
            long long o1 = coff + (long long)(row + 8) * ldc + col;
            if (OUTM == 0) {
                *(float2*)(C + o0) = make_float2(v0, v1);
                *(float2*)(C + o1) = make_float2(v2, v3);
            } else if (OUTM == 1) {
                *(hf2*)(Chi + o0) = __floats2half2_rn(v0, v1);
                *(hf2*)(Chi + o1) = __floats2half2_rn(v2, v3);
            } else {
                hf2 h, l;
                split_pair(v0, v1, h, l);
                *(hf2*)(Chi + o0) = h; *(hf2*)(Clo + o0) = l;
                split_pair(v2, v3, h, l);
                *(hf2*)(Chi + o1) = h; *(hf2*)(Clo + o1) = l;
            }
        }
    }
}

/* ---------------- fused flash MHA (QK^T + softmax + PV) --------------------
   R12: Q and P single fp16 (halved MMAs vs R10); K, V single fp16.
   Smem request kept at R10's 132096 to pin occupancy at 1 CTA/SM.           */
__global__ void __launch_bounds__(256, 1) flash_mha(
    const hf* __restrict__ QKVhi, hf* __restrict__ Ohi)
{
    extern __shared__ char dsm[];
    unsigned smRaw = (unsigned)__cvta_generic_to_shared(dsm);
    unsigned smQ  = (smRaw + 1023u) & ~1023u;    /* 16K */
    unsigned smKV = smQ + 16384;                 /* 3 stages x [KH 16K | VH 16K] */

    int bh = blockIdx.y;
    int b = bh >> 4, h = bh & 15;
    long long rowBase = (long long)b * NTOK;
    int qRow0 = blockIdx.x * 128;
    const int ld = 3 * DIMC;
    int qcol = h * 64, kcol = DIMC + h * 64, vcol = 2 * DIMC + h * 64;

    int tid = threadIdx.x, lane = tid & 31, w = tid >> 5;

    #pragma unroll
    for (int i = 0; i < 4; i++) {
        int li = tid + i * 256, r = li >> 3, ch = li & 7;
        unsigned sw = r * 128 + ((ch ^ (r & 7)) << 4);
        cpa16(smQ + sw, QKVhi + (rowBase + qRow0 + r) * ld + qcol + ch * 8);
    }
    CP_COMMIT();

    auto issueKV = [&](int s, int kt0) {
        unsigned base = smKV + s * 32768;
        #pragma unroll
        for (int i = 0; i < 4; i++) {
            int li = tid + i * 256, r = li >> 3, ch = li & 7;
            unsigned sw = r * 128 + ((ch ^ (r & 7)) << 4);
            long long g = (rowBase + kt0 + r) * ld;
            cpa16(base + sw,         QKVhi + g + kcol + ch * 8);
            cpa16(base + 16384 + sw, QKVhi + g + vcol + ch * 8);
        }
    };

    issueKV(0, 0);   CP_COMMIT();
    issueKV(1, 128); CP_COMMIT();

    CP_WAIT2();
    __syncthreads();

    unsigned qh[4][4];
    {
        int ar = w * 16 + (lane & 15);
        hf2 s2 = __floats2half2_rn(0.125f, 0.125f);
        #pragma unroll
        for (int c = 0; c < 4; c++) {
            int ac = c * 2 + (lane >> 4);
            ldsm4(qh[c][0], qh[c][1], qh[c][2], qh[c][3],
                  smQ + ar * 128 + ((ac ^ (ar & 7)) << 4));
            #pragma unroll
            for (int r = 0; r < 4; r++) {
                hf2 t = *(hf2*)&qh[c][r]; t = __hmul2(t, s2); qh[c][r] = *(unsigned*)&t;
            }
        }
    }

    float o[8][4] = {};
    float l0 = 0.f, l1 = 0.f;

    for (int kt = 0; kt < 16; kt++) {
        CP_WAIT1();
        __syncthreads();
        if (kt + 2 < 16) issueKV((kt + 2) % 3, (kt + 2) * 128);
        CP_COMMIT();

        unsigned base = smKV + (kt % 3) * 32768;

        float sacc[16][4] = {};
        #pragma unroll
        for (int c = 0; c < 4; c++) {
            #pragma unroll
            for (int np = 0; np < 8; np++) {
                unsigned kh2[2][2];
                int br = np * 16 + ((lane >> 4) << 3) + (lane & 7);
                int kc = c * 2 + ((lane >> 3) & 1);
                ldsm4(kh2[0][0], kh2[0][1], kh2[1][0], kh2[1][1],
                      base + br * 128 + ((kc ^ (br & 7)) << 4));
                #pragma unroll
                for (int j = 0; j < 2; j++) mma16816(sacc[2*np+j], qh[c], kh2[j]);
            }
        }

        unsigned ph[8][4];
        #pragma unroll
        for (int f = 0; f < 16; f++) {
            float p0 = __expf(sacc[f][0]);
            float p1 = __expf(sacc[f][1]);
            float p2 = __expf(sacc[f][2]);
            float p3 = __expf(sacc[f][3]);
            l0 += p0 + p1;
            l1 += p2 + p3;
            int j = f >> 1, hfi = f & 1;
            hf2 a = __floats2half2_rn(p0, p1);
            hf2 c = __floats2half2_rn(p2, p3);
            ph[j][hfi*2+0] = *(unsigned*)&a;
            ph[j][hfi*2+1] = *(unsigned*)&c;
        }

        unsigned vb = base + 16384;
        #pragma unroll
        for (int j = 0; j < 8; j++) {
            #pragma unroll
            for (int np2 = 0; np2 < 4; np2++) {
                unsigned vh[2][2];
                int bk = j * 16 + (lane & 15);
                int nc = (np2 * 16 + ((lane >> 4) << 3)) >> 3;
                ldsm4t(vh[0][0], vh[0][1], vh[1][0], vh[1][1],
                       vb + bk * 128 + ((nc ^ (bk & 7)) << 4));
                #pragma unroll
                for (int t = 0; t < 2; t++) mma16816(o[2*np2+t], ph[j], vh[t]);
            }
        }
    }

    l0 += __shfl_xor_sync(0xffffffffu, l0, 1);
    l0 += __shfl_xor_sync(0xffffffffu, l0, 2);
    l1 += __shfl_xor_sync(0xffffffffu, l1, 1);
    l1 += __shfl_xor_sync(0xffffffffu, l1, 2);
    float i0 = 1.0f / l0, i1 = 1.0f / l1;

    long long or0 = (rowBase + qRow0 + w * 16 + (lane >> 2)) * DIMC + h * 64;
    #pragma unroll
    for (int nf = 0; nf < 8; nf++) {
        int col = nf * 8 + (lane & 3) * 2;
        *(hf2*)(Ohi + or0 + col)            = __floats2half2_rn(o[nf][0] * i0, o[nf][1] * i0);
        *(hf2*)(Ohi + or0 + 8 * DIMC + col) = __floats2half2_rn(o[nf][2] * i1, o[nf][3] * i1);
    }
}

/* ---------------- fp32 -> fp16 convert (weights) --------------------------- */
__global__ void __launch_bounds__(256) conv_vec(
    const float* __restrict__ in, hf* __restrict__ hi)
{
    long long i = ((long long)blockIdx.x * 256 + threadIdx.x) * 4;
    float4 v = *(const float4*)(in + i);
    *(hf2*)(hi + i)     = __floats2half2_rn(v.x, v.y);
    *(hf2*)(hi + i + 2) = __floats2half2_rn(v.z, v.w);
}

/* ---------------- theta + softmax -> fp16 hi/lo --------------------------- */
__global__ void __launch_bounds__(256) theta_softmax2048_hf(
    const float* __restrict__ S, hf* __restrict__ Phi, hf* __restrict__ Plo)
{
    __shared__ float red[8];
    const float* row = S + (long long)blockIdx.x * 2048;
    long long ob = (long long)blockIdx.x * 2048;
    int tid = threadIdx.x;
    float4 v0 = ((const float4*)row)[tid];
    float4 v1 = ((const float4*)row)[tid + 256];
    v0.x = theta_fn(v0.x); v0.y = theta_fn(v0.y); v0.z = theta_fn(v0.z); v0.w = theta_fn(v0.w);
    v1.x = theta_fn(v1.x); v1.y = theta_fn(v1.y); v1.z = theta_fn(v1.z); v1.w = theta_fn(v1.w);
    float m = fmaxf(fmaxf(fmaxf(v0.x, v0.y), fmaxf(v0.z, v0.w)),
                    fmaxf(fmaxf(v1.x, v1.y), fmaxf(v1.z, v1.w)));
    #pragma unroll
    for (int o = 16; o; o >>= 1) m = fmaxf(m, __shfl_xor_sync(0xffffffffu, m, o));
    if ((tid & 31) == 0) red[tid >> 5] = m;
    __syncthreads();
    m = fmaxf(fmaxf(fmaxf(red[0], red[1]), fmaxf(red[2], red[3])),
              fmaxf(fmaxf(red[4], red[5]), fmaxf(red[6], red[7])));
    v0.x = __expf(v0.x - m); v0.y = __expf(v0.y - m); v0.z = __expf(v0.z - m); v0.w = __expf(v0.w - m);
    v1.x = __expf(v1.x - m); v1.y = __expf(v1.y - m); v1.z = __expf(v1.z - m); v1.w = __expf(v1.w - m);
    float s = v0.x + v0.y + v0.z + v0.w + v1.x + v1.y + v1.z + v1.w;
    #pragma unroll
    for (int o = 16; o; o >>= 1) s += __shfl_xor_sync(0xffffffffu, s, o);
    __syncthreads();
    if ((tid & 31) == 0) red[tid >> 5] = s;
    __syncthreads();
    s = red[0] + red[1] + red[2] + red[3] + red[4] + red[5] + red[6] + red[7];
    float r = 1.0f / s;
    v0.x *= r; v0.y *= r; v0.z *= r; v0.w *= r;
    v1.x *= r; v1.y *= r; v1.z *= r; v1.w *= r;
    hf2 h0, l0, h1, l1;
    split_pair(v0.x, v0.y, h0, l0); split_pair(v0.z, v0.w, h1, l1);
    *(hf2*)(Phi + ob + tid*4)     = h0; *(hf2*)(Phi + ob + tid*4 + 2) = h1;
    *(hf2*)(Plo + ob + tid*4)     = l0; *(hf2*)(Plo + ob + tid*4 + 2) = l1;
    split_pair(v1.x, v1.y, h0, l0); split_pair(v1.z, v1.w, h1, l1);
    *(hf2*)(Phi + ob + 1024 + tid*4)     = h0; *(hf2*)(Phi + ob + 1024 + tid*4 + 2) = h1;
    *(hf2*)(Plo + ob + 1024 + tid*4)     = l0; *(hf2*)(Plo + ob + 1024 + tid*4 + 2) = l1;
}

/* ---------------- LayerNorm over 1024 -> fp16 ----------------------------- */
__global__ void __launch_bounds__(256) layernorm1024_hf(
    const float* __restrict__ X, const float* __restrict__ g,
    const float* __restrict__ bta, hf* __restrict__ Yhi)
{
    __shared__ float rs[8], rq[8];
    long long base = (long long)blockIdx.x * 1024;
    int tid = threadIdx.x;
    float4 v = *(const float4*)(X + base + tid * 4);
    float s = v.x + v.y + v.z + v.w;
    float q = v.x*v.x + v.y*v.y + v.z*v.z + v.w*v.w;
    #pragma unroll
    for (int o = 16; o; o >>= 1) {
        s += __shfl_xor_sync(0xffffffffu, s, o);
        q += __shfl_xor_sync(0xffffffffu, q, o);
    }
    if ((tid & 31) == 0) { rs[tid >> 5] = s; rq[tid >> 5] = q; }
    __syncthreads();
    s = rs[0] + rs[1] + rs[2] + rs[3] + rs[4] + rs[5] + rs[6] + rs[7];
    q = rq[0] + rq[1] + rq[2] + rq[3] + rq[4] + rq[5] + rq[6] + rq[7];
    float mu  = s * (1.0f / 1024.0f);
    float var = q * (1.0f / 1024.0f) - mu * mu;
    float inv = rsqrtf(var + 1e-5f);
    float4 gg = *(const float4*)(g + tid * 4);
    float4 bb = *(const float4*)(bta + tid * 4);
    float o0 = (v.x - mu) * inv * gg.x + bb.x;
    float o1 = (v.y - mu) * inv * gg.y + bb.y;
    float o2 = (v.z - mu) * inv * gg.z + bb.z;
    float o3 = (v.w - mu) * inv * gg.w + bb.w;
    *(hf2*)(Yhi + base + tid*4)     = __floats2half2_rn(o0, o1);
    *(hf2*)(Yhi + base + tid*4 + 2) = __floats2half2_rn(o2, o3);
}

/* ---------------- residual adds ------------------------------------------- */
__global__ void __launch_bounds__(256) add_hf(
    float* __restrict__ out, const float* __restrict__ a, const float* __restrict__ b,
    hf* __restrict__ hi)
{
    long long i = ((long long)blockIdx.x * 256 + threadIdx.x) * 4;
    float4 av = *(const float4*)(a + i);
    float4 bv = *(const float4*)(b + i);
    av.x += bv.x; av.y += bv.y; av.z += bv.z; av.w += bv.w;
    *(float4*)(out + i) = av;
    *(hf2*)(hi + i)     = __floats2half2_rn(av.x, av.y);
    *(hf2*)(hi + i + 2) = __floats2half2_rn(av.z, av.w);
}
__global__ void __launch_bounds__(256) add_plain(
    float* __restrict__ out, const float* __restrict__ b)
{
    long long i = ((long long)blockIdx.x * 256 + threadIdx.x) * 4;
    float4 av = *(const float4*)(out + i);
    float4 bv = *(const float4*)(b + i);
    av.x += bv.x; av.y += bv.y; av.z += bv.z; av.w += bv.w;
    *(float4*)(out + i) = av;
}

/* ---------------- host-side dispatch -------------------------------------- */
#define SMEM_SN    148480   /* single-A NN: 3*(16384+32768) + 1024 */
#define SMEM_AS_NN 99328    /* split-A NN:  3*(16384+16384) + 1024 */
#define SMEM_AS_TB 148480   /* split-A TB:  3*(16384+32768) + 1024 */
#define SMEM_FLASH 132096   /* needs 115712; padded to pin 1 CTA/SM (R10 parity) */

extern "C" void kernel_launch(void* const* d_in, const int* in_sizes, int n_in,
                              void* d_out, int out_size)
{
    const float* x     = (const float*)d_in[0];
    const float* ln1_g = (const float*)d_in[1];
    const float* ln1_b = (const float*)d_in[2];
    const float* qkv_w = (const float*)d_in[3];
    const float* qkv_b = (const float*)d_in[4];
    const float* proj_w= (const float*)d_in[5];
    const float* proj_b= (const float*)d_in[6];
    const float* kq_w  = (const float*)d_in[7];
    const float* kq_b  = (const float*)d_in[8];
    const float* kk_w  = (const float*)d_in[9];
    const float* kk_b  = (const float*)d_in[10];
    const float* kv_w  = (const float*)d_in[11];
    const float* kv_b  = (const float*)d_in[12];
    const float* ko_w  = (const float*)d_in[13];
    const float* ko_b  = (const float*)d_in[14];
    const float* ln2_g = (const float*)d_in[15];
    const float* ln2_b = (const float*)d_in[16];
    const float* fc1_w = (const float*)d_in[17];
    const float* fc1_b = (const float*)d_in[18];
    const float* fc2_w = (const float*)d_in[19];
    const float* fc2_b = (const float*)d_in[20];
    float* out = (float*)d_out;

    float *sc, *bufA;
    hf *whi, *lnhi, *qkvhi, *qkvlo, *schi, *sclo, *aohi, *reshi, *ffhi;
    cudaGetSymbolAddress((void**)&sc,    g_sc);
    cudaGetSymbolAddress((void**)&bufA,  g_bufA);
    cudaGetSymbolAddress((void**)&whi,   g_whi);
    cudaGetSymbolAddress((void**)&lnhi,  g_lnhi);
    cudaGetSymbolAddress((void**)&qkvhi, g_qkvhi);
    cudaGetSymbolAddress((void**)&qkvlo, g_qkvlo);
    cudaGetSymbolAddress((void**)&schi,  g_schi);
    cudaGetSymbolAddress((void**)&sclo,  g_sclo);
    cudaGetSymbolAddress((void**)&aohi,  g_aohi);
    cudaGetSymbolAddress((void**)&reshi, g_reshi);
    cudaGetSymbolAddress((void**)&ffhi,  g_ffhi);

    cudaFuncSetAttribute(bgemm<256, false, false, false, 2>, cudaFuncAttributeMaxDynamicSharedMemorySize, SMEM_SN);
    cudaFuncSetAttribute(bgemm<256, false, false, false, 1>, cudaFuncAttributeMaxDynamicSharedMemorySize, SMEM_SN);
    cudaFuncSetAttribute(bgemm<256, false, false, false, 0>, cudaFuncAttributeMaxDynamicSharedMemorySize, SMEM_SN);
    cudaFuncSetAttribute(bgemm<256, false, false, true,  1>, cudaFuncAttributeMaxDynamicSharedMemorySize, SMEM_SN);
    cudaFuncSetAttribute(bgemm<256, true,  true,  false, 0>, cudaFuncAttributeMaxDynamicSharedMemorySize, SMEM_AS_TB);
    cudaFuncSetAttribute(bgemm<256, false, true,  false, 1>, cudaFuncAttributeMaxDynamicSharedMemorySize, SMEM_AS_NN);
    cudaFuncSetAttribute(flash_mha, cudaFuncAttributeMaxDynamicSharedMemorySize, SMEM_FLASH);

    const long long NN = (long long)NTOK * NTOK;
    const long long TC = (long long)NTOK * DIMC;
    const int nElemBlks = (TTOK * DIMC) / (4 * 256);
    dim3 tb(256);

    /* launches 1-5 (launch #6 = QKV GEMM for ncu -s 5 -c 1) */
    conv_vec<<<3072, tb>>>(qkv_w,  whi + W_QKV);
    conv_vec<<<1024, tb>>>(proj_w, whi + W_PROJ);
    conv_vec<<<1024, tb>>>(kq_w,   whi + W_KQ);
    conv_vec<<<1024, tb>>>(kk_w,   whi + W_KK);
    layernorm1024_hf<<<TTOK, tb>>>(x, ln1_g, ln1_b, lnhi);

    /* launch #6: qkv = ln1 @ qkv_w + b (single-A; hi-only output) */
    bgemm<256, false, false, false, 1><<<dim3(12, 32, 1), tb, SMEM_SN>>>(
        lnhi, nullptr, whi + W_QKV, nullptr, qkvhi, nullptr, qkv_b,
        1024, 1024, 3072, 3072, 1, 0,0, 0,0, 0,0, 1.0f);

    conv_vec<<<1024, tb>>>(kv_w,   whi + W_KV);
    conv_vec<<<1024, tb>>>(ko_w,   whi + W_KO);
    conv_vec<<<4096, tb>>>(fc1_w,  whi + W_FC1);
    conv_vec<<<4096, tb>>>(fc2_w,  whi + W_FC2);

    /* fused MHA attention -> aohi (single-fp16 Q/P) */
    flash_mha<<<dim3(16, 32), tb, SMEM_FLASH>>>(qkvhi, aohi);

    bgemm<256, false, false, false, 0><<<dim3(4, 32, 1), tb, SMEM_SN>>>(
        aohi, nullptr, whi + W_PROJ, bufA, nullptr, nullptr, proj_b,
        1024, 1024, 1024, 1024, 1, 0,0, 0,0, 0,0, 1.0f);
    add_hf<<<nElemBlks, tb>>>(out, x, bufA, reshi);

    /* ---- sublayer 2: kernel attention (R10 structure, split-A) ---- */
    hf* bqhi = qkvhi;                       hf* bqlo = qkvlo;
    hf* bkhi = qkvhi + (size_t)TTOK*DIMC;
    hf* bvhi = qkvhi + (size_t)2*TTOK*DIMC;

    /* q needs hi/lo (feeds split-A QK); k, v single */
    bgemm<256, false, false, false, 2><<<dim3(4, 32, 1), tb, SMEM_SN>>>(
        reshi, nullptr, whi + W_KQ, nullptr, bqhi, bqlo, kq_b,
        1024, 1024, 1024, 1024, 1, 0,0, 0,0, 0,0, 1.0f);
    bgemm<256, false, false, false, 1><<<dim3(4, 32, 1), tb, SMEM_SN>>>(
        reshi, nullptr, whi + W_KK, nullptr, bkhi, nullptr, kk_b,
        1024, 1024, 1024, 1024, 1, 0,0, 0,0, 0,0, 1.0f);
    bgemm<256, false, false, false, 1><<<dim3(4, 32, 1), tb, SMEM_SN>>>(
        reshi, nullptr, whi + W_KV, nullptr, bvhi, nullptr, kv_b,
        1024, 1024, 1024, 1024, 1, 0,0, 0,0, 0,0, 1.0f);

    /* qk = q @ k^T per batch (A split, B single) */
    bgemm<256, true, true, false, 0><<<dim3(8, 16, BATCHN), tb, SMEM_AS_TB>>>(
        bqhi, bqlo, bkhi, sc, nullptr, nullptr, nullptr,
        1024, 1024, 1024, NTOK, 1, TC, 0, TC, 0, NN, 0, 1.0f);

    theta_softmax2048_hf<<<BATCHN*NTOK, tb>>>(sc, schi, sclo);

    /* av = attn @ v per batch (A = P split, B single) */
    bgemm<256, false, true, false, 1><<<dim3(4, 16, BATCHN), tb, SMEM_AS_NN>>>(
        schi, sclo, bvhi, nullptr, aohi, nullptr, nullptr,
        NTOK, NTOK, DIMC, DIMC, 1, NN, 0, TC, 0, TC, 0, 1.0f);

    bgemm<256, false, false, false, 0><<<dim3(4, 32, 1), tb, SMEM_SN>>>(
        aohi, nullptr, whi + W_KO, bufA, nullptr, nullptr, ko_b,
        1024, 1024, 1024, 1024, 1, 0,0, 0,0, 0,0, 1.0f);
    add_plain<<<nElemBlks, tb>>>(out, bufA);

    /* ---- sublayer 3: FFN ---- */
    layernorm1024_hf<<<TTOK, tb>>>(out, ln2_g, ln2_b, lnhi);
    bgemm<256, false, false, true, 1><<<dim3(16, 32, 1), tb, SMEM_SN>>>(
        lnhi, nullptr, whi + W_FC1, nullptr, ffhi, nullptr, fc1_b,
        1024, 1024, 4096, 4096, 1, 0,0, 0,0, 0,0, 1.0f);
    bgemm<256, false, false, false, 0><<<dim3(4, 32, 1), tb, SMEM_SN>>>(
        ffhi, nullptr, whi + W_FC2, bufA, nullptr, nullptr, fc2_b,
        4096, 4096, 1024, 1024, 1, 0,0, 0,0, 0,0, 1.0f);
    add_plain<<<nElemBlks, tb>>>(out, bufA);
}

// round 14
// speedup vs baseline: 1.5013x; 1.1220x over previous
#include <cuda_runtime.h>
#include <cuda_fp16.h>
#include <math.h>

#define DIMC 1024
#define NTOK 2048
#define BATCHN 2
#define TTOK (BATCHN*NTOK)
#define NHEADS 16
#define HDIM 64
#define DFF 4096

typedef __half hf;
typedef __half2 hf2;

/* ---------------- scratch (device globals; no allocations allowed) -------- */
__device__ float g_sc  [(size_t)BATCHN*NTOK*NTOK];          /* 32 MB kernel-attn scores */
__device__ float g_bufA[(size_t)TTOK*DIMC];                 /* 16 MB fp32 */
__device__ hf g_whi[16777216];
__device__ hf g_lnhi [(size_t)TTOK*DIMC];
__device__ hf g_qkvhi[(size_t)TTOK*3*DIMC];
__device__ hf g_schi [(size_t)BATCHN*NTOK*NTOK];
__device__ hf g_aohi [(size_t)TTOK*DIMC];
__device__ hf g_reshi[(size_t)TTOK*DIMC];
__device__ hf g_ffhi [(size_t)TTOK*DFF];

#define W_QKV  0LL
#define W_PROJ 3145728LL
#define W_KQ   4194304LL
#define W_KK   5242880LL
#define W_KV   6291456LL
#define W_KO   7340032LL
#define W_FC1  8388608LL
#define W_FC2  12582912LL

/* ---------------- helpers ------------------------------------------------- */
__device__ __forceinline__ float gelu_f(float x) {
    return 0.5f * x * (1.0f + erff(x * 0.7071067811865476f));
}
__device__ __forceinline__ float theta_fn(float x) {
    float sg = 1.0f / (1.0f + __expf(-x));
    float rl = fmaxf(x, 0.0f);
    return 0.5f + 0.2f * sg + 0.15f * tanhf(x) + 0.1f * rl;
}
__device__ __forceinline__ void ldsm4(unsigned& r0, unsigned& r1, unsigned& r2, unsigned& r3, unsigned a) {
    asm volatile("ldmatrix.sync.aligned.m8n8.x4.shared.b16 {%0,%1,%2,%3}, [%4];"
                 : "=r"(r0), "=r"(r1), "=r"(r2), "=r"(r3) : "r"(a));
}
__device__ __forceinline__ void ldsm4t(unsigned& r0, unsigned& r1, unsigned& r2, unsigned& r3, unsigned a) {
    asm volatile("ldmatrix.sync.aligned.m8n8.x4.trans.shared.b16 {%0,%1,%2,%3}, [%4];"
                 : "=r"(r0), "=r"(r1), "=r"(r2), "=r"(r3) : "r"(a));
}
__device__ __forceinline__ void mma16816(float* d, const unsigned* a, const unsigned* b) {
    asm volatile(
        "mma.sync.aligned.m16n8k16.row.col.f32.f16.f16.f32 "
        "{%0,%1,%2,%3}, {%4,%5,%6,%7}, {%8,%9}, {%0,%1,%2,%3};"
        : "+f"(d[0]), "+f"(d[1]), "+f"(d[2]), "+f"(d[3])
        : "r"(a[0]), "r"(a[1]), "r"(a[2]), "r"(a[3]), "r"(b[0]), "r"(b[1]));
}
__device__ __forceinline__ void cpa16(unsigned dst, const void* src) {
    asm volatile("cp.async.cg.shared.global [%0], [%1], 16;" :: "r"(dst), "l"(src));
}
#define CP_COMMIT() asm volatile("cp.async.commit_group;")
#define CP_WAIT1()  asm volatile("cp.async.wait_group 1;")
#define CP_WAIT2()  asm volatile("cp.async.wait_group 2;")

/* ---------------- fp16 tensor-core GEMM (cp.async 3-stage, k-tile 64) -----
   C[z] = alpha * A[z](M x K) * op(B[z]) + bias ; op = B [K,N] (NN) or B^T (TB)
   A, B single RN fp16. OUTM: 0 = fp32 C, 1 = fp16 Chi.
   M%128==0, N%256==0 (NTILE=256), K%64==0.                                 */
template<int NTILE, bool TB, bool GELU, int OUTM>
__global__ void __launch_bounds__(256, 1) bgemm(
    const hf* __restrict__ Ahi, const hf* __restrict__ Bhi,
    float* __restrict__ C, hf* __restrict__ Chi,
    const float* __restrict__ bias,
    int K, int lda, int ldb, int ldc, int zdiv,
    long long sA1, long long sA2, long long sB1, long long sB2,
    long long sC1, long long sC2, float alpha)
{
    extern __shared__ char dsm[];
    constexpr int KT     = 64;
    constexpr int ABYTES = 16384;            /* 128 rows x 128B */
    constexpr int BBYTES = NTILE * 128;      /* TB: NTILE rows x 128B ; NN: 64 rows x NTILE*2 */
    constexpr int STAGE  = ABYTES + BBYTES;

    unsigned smRaw  = (unsigned)__cvta_generic_to_shared(dsm);
    unsigned smBase = (smRaw + 1023u) & ~1023u;

    int z = blockIdx.z, z1 = z / zdiv, z2 = z % zdiv;
    const hf* Ah = Ahi + z1 * sA1 + z2 * sA2;
    const hf* Bh = Bhi + z1 * sB1 + z2 * sB2;
    long long coff = z1 * sC1 + z2 * sC2;

    int rowBase = blockIdx.y * 128;
    int colBase = blockIdx.x * NTILE;
    int tid = threadIdx.x, lane = tid & 31, w = tid >> 5;

    constexpr int MF = 4;                 /* warp tile 64 x (NTILE/4) */
    constexpr int NF = NTILE / 32;        /* 8 */
    int warpRow = (w & 1) * 64;
    int warpCol = (w >> 1) * (NTILE / 4);

    float acc[MF][NF][4] = {};

    auto issue = [&](int s, int k0) {
        unsigned sA = smBase + s * STAGE;
        unsigned sB = sA + ABYTES;
        #pragma unroll
        for (int i = 0; i < 4; i++) {
            int li = tid + i * 256, r = li >> 3, ch = li & 7;
            const hf* src = Ah + (long long)(rowBase + r) * lda + k0 + ch * 8;
            cpa16(sA + r * 128 + ((ch ^ (r & 7)) << 4), src);
        }
        if (TB) {
            #pragma unroll
            for (int i = 0; i < NTILE / 32; i++) {
                int li = tid + i * 256, r = li >> 3, ch = li & 7;
                const hf* src = Bh + (long long)(colBase + r) * ldb + k0 + ch * 8;
                cpa16(sB + r * 128 + ((ch ^ (r & 7)) << 4), src);
            }
        } else {
            constexpr int CPR = NTILE / 8;            /* 16B chunks per B row */
            #pragma unroll
            for (int i = 0; i < (64 * CPR) / 256; i++) {
                int li = tid + i * 256;
                int r = li / CPR, ch = li % CPR;
                const hf* src = Bh + (long long)(k0 + r) * ldb + colBase + ch * 8;
                cpa16(sB + r * (NTILE * 2) + ((ch ^ (r & 7)) << 4), src);
            }
        }
    };

    auto compute = [&](int s) {
        unsigned sA = smBase + s * STAGE;
        unsigned sB = sA + ABYTES;
        #pragma unroll
        for (int ks = 0; ks < 4; ks++) {
            unsigned ah[MF][4];
            #pragma unroll
            for (int mf = 0; mf < MF; mf++) {
                int ar = warpRow + mf * 16 + (lane & 15);
                int ac = ks * 2 + (lane >> 4);
                ldsm4(ah[mf][0], ah[mf][1], ah[mf][2], ah[mf][3],
                      sA + ar * 128 + ((ac ^ (ar & 7)) << 4));
            }
            #pragma unroll
            for (int np = 0; np < NF / 2; np++) {
                unsigned bh[2][2];
                if (!TB) {
                    int bk = ks * 16 + (lane & 15);
                    int nc = (warpCol + np * 16 + ((lane >> 4) << 3)) >> 3;
                    ldsm4t(bh[0][0], bh[0][1], bh[1][0], bh[1][1],
                           sB + bk * (NTILE * 2) + ((nc ^ (bk & 7)) << 4));
                } else {
                    int br = warpCol + np * 16 + ((lane >> 4) << 3) + (lane & 7);
                    int kc = ks * 2 + ((lane >> 3) & 1);
                    ldsm4(bh[0][0], bh[0][1], bh[1][0], bh[1][1],
                          sB + br * 128 + ((kc ^ (br & 7)) << 4));
                }
                #pragma unroll
                for (int mf = 0; mf < MF; mf++)
                    #pragma unroll
                    for (int j = 0; j < 2; j++) mma16816(acc[mf][2*np+j], ah[mf], bh[j]);
            }
        }
    };

    int nk = K / KT;
    issue(0, 0); CP_COMMIT();
    if (nk > 1) issue(1, KT);
    CP_COMMIT();
    for (int i = 0; i < nk; i++) {
        CP_WAIT1();
        __syncthreads();
        if (i + 2 < nk) issue((i + 2) % 3, (i + 2) * KT);
        CP_COMMIT();
        compute(i % 3);
    }

    #pragma unroll
    for (int mf = 0; mf < MF; mf++) {
        #pragma unroll
        for (int nf = 0; nf < NF; nf++) {
            int row = rowBase + warpRow + mf * 16 + (lane >> 2);
            int col = colBase + warpCol + nf * 8 + (lane & 3) * 2;
            float bx = 0.f, by = 0.f;
            if (bias) { float2 bb = *(const float2*)(bias + col); bx = bb.x; by = bb.y; }
            float v0 = acc[mf][nf][0] * alpha + bx;
            float v1 = acc[mf][nf][1] * alpha + by;
            float v2 = acc[mf][nf][2] * alpha + bx;
            float v3 = acc[mf][nf][3] * alpha + by;
            if (GELU) { v0 = gelu_f(v0); v1 = gelu_f(v1); v2 = gelu_f(v2); v3 = gelu_f(v3); }
            long long o0 = coff + (long long)row * ldc + col;
            long long o1 = coff + (long long)(row + 8) * ldc + col;
            if (OUTM == 0) {
                *(float2*)(C + o0) = make_float2(v0, v1);
                *(float2*)(C + o1) = make_float2(v2, v3);
            } else {
                *(hf2*)(Chi + o0) = __floats2half2_rn(v0, v1);
                *(hf2*)(Chi + o1) = __floats2half2_rn(v2, v3);
            }
        }
    }
}

/* ---------------- fused flash MHA (QK^T + softmax + PV), single fp16 ------
   Smem request padded to 132096 to pin 1 CTA/SM (R12-verified).            */
__global__ void __launch_bounds__(256, 1) flash_mha(
    const hf* __restrict__ QKVhi, hf* __restrict__ Ohi)
{
    extern __shared__ char dsm[];
    unsigned smRaw = (unsigned)__cvta_generic_to_shared(dsm);
    unsigned smQ  = (smRaw + 1023u) & ~1023u;    /* 16K */
    unsigned smKV = smQ + 16384;                 /* 3 stages x [KH 16K | VH 16K] */

    int bh = blockIdx.y;
    int b = bh >> 4, h = bh & 15;
    long long rowBase = (long long)b * NTOK;
    int qRow0 = blockIdx.x * 128;
    const int ld = 3 * DIMC;
    int qcol = h * 64, kcol = DIMC + h * 64, vcol = 2 * DIMC + h * 64;

    int tid = threadIdx.x, lane = tid & 31, w = tid >> 5;

    #pragma unroll
    for (int i = 0; i < 4; i++) {
        int li = tid + i * 256, r = li >> 3, ch = li & 7;
        unsigned sw = r * 128 + ((ch ^ (r & 7)) << 4);
        cpa16(smQ + sw, QKVhi + (rowBase + qRow0 + r) * ld + qcol + ch * 8);
    }
    CP_COMMIT();

    auto issueKV = [&](int s, int kt0) {
        unsigned base = smKV + s * 32768;
        #pragma unroll
        for (int i = 0; i < 4; i++) {
            int li = tid + i * 256, r = li >> 3, ch = li & 7;
            unsigned sw = r * 128 + ((ch ^ (r & 7)) << 4);
            long long g = (rowBase + kt0 + r) * ld;
            cpa16(base + sw,         QKVhi + g + kcol + ch * 8);
            cpa16(base + 16384 + sw, QKVhi + g + vcol + ch * 8);
        }
    };

    issueKV(0, 0);   CP_COMMIT();
    issueKV(1, 128); CP_COMMIT();

    CP_WAIT2();
    __syncthreads();

    unsigned qh[4][4];
    {
        int ar = w * 16 + (lane & 15);
        hf2 s2 = __floats2half2_rn(0.125f, 0.125f);
        #pragma unroll
        for (int c = 0; c < 4; c++) {
            int ac = c * 2 + (lane >> 4);
            ldsm4(qh[c][0], qh[c][1], qh[c][2], qh[c][3],
                  smQ + ar * 128 + ((ac ^ (ar & 7)) << 4));
            #pragma unroll
            for (int r = 0; r < 4; r++) {
                hf2 t = *(hf2*)&qh[c][r]; t = __hmul2(t, s2); qh[c][r] = *(unsigned*)&t;
            }
        }
    }

    float o[8][4] = {};
    float l0 = 0.f, l1 = 0.f;

    for (int kt = 0; kt < 16; kt++) {
        CP_WAIT1();
        __syncthreads();
        if (kt + 2 < 16) issueKV((kt + 2) % 3, (kt + 2) * 128);
        CP_COMMIT();

        unsigned base = smKV + (kt % 3) * 32768;

        float sacc[16][4] = {};
        #pragma unroll
        for (int c = 0; c < 4; c++) {
            #pragma unroll
            for (int np = 0; np < 8; np++) {
                unsigned kh2[2][2];
                int br = np * 16 + ((lane >> 4) << 3) + (lane & 7);
                int kc = c * 2 + ((lane >> 3) & 1);
                ldsm4(kh2[0][0], kh2[0][1], kh2[1][0], kh2[1][1],
                      base + br * 128 + ((kc ^ (br & 7)) << 4));
                #pragma unroll
                for (int j = 0; j < 2; j++) mma16816(sacc[2*np+j], qh[c], kh2[j]);
            }
        }

        unsigned ph[8][4];
        #pragma unroll
        for (int f = 0; f < 16; f++) {
            float p0 = __expf(sacc[f][0]);
            float p1 = __expf(sacc[f][1]);
            float p2 = __expf(sacc[f][2]);
            float p3 = __expf(sacc[f][3]);
            l0 += p0 + p1;
            l1 += p2 + p3;
            int j = f >> 1, hfi = f & 1;
            hf2 a = __floats2half2_rn(p0, p1);
            hf2 c = __floats2half2_rn(p2, p3);
            ph[j][hfi*2+0] = *(unsigned*)&a;
            ph[j][hfi*2+1] = *(unsigned*)&c;
        }

        unsigned vb = base + 16384;
        #pragma unroll
        for (int j = 0; j < 8; j++) {
            #pragma unroll
            for (int np2 = 0; np2 < 4; np2++) {
                unsigned vh[2][2];
                int bk = j * 16 + (lane & 15);
                int nc = (np2 * 16 + ((lane >> 4) << 3)) >> 3;
                ldsm4t(vh[0][0], vh[0][1], vh[1][0], vh[1][1],
                       vb + bk * 128 + ((nc ^ (bk & 7)) << 4));
                #pragma unroll
                for (int t = 0; t < 2; t++) mma16816(o[2*np2+t], ph[j], vh[t]);
            }
        }
    }

    l0 += __shfl_xor_sync(0xffffffffu, l0, 1);
    l0 += __shfl_xor_sync(0xffffffffu, l0, 2);
    l1 += __shfl_xor_sync(0xffffffffu, l1, 1);
    l1 += __shfl_xor_sync(0xffffffffu, l1, 2);
    float i0 = 1.0f / l0, i1 = 1.0f / l1;

    long long or0 = (rowBase + qRow0 + w * 16 + (lane >> 2)) * DIMC + h * 64;
    #pragma unroll
    for (int nf = 0; nf < 8; nf++) {
        int col = nf * 8 + (lane & 3) * 2;
        *(hf2*)(Ohi + or0 + col)            = __floats2half2_rn(o[nf][0] * i0, o[nf][1] * i0);
        *(hf2*)(Ohi + or0 + 8 * DIMC + col) = __floats2half2_rn(o[nf][2] * i1, o[nf][3] * i1);
    }
}

/* ---------------- fp32 -> fp16 convert (weights) --------------------------- */
__global__ void __launch_bounds__(256) conv_vec(
    const float* __restrict__ in, hf* __restrict__ hi)
{
    long long i = ((long long)blockIdx.x * 256 + threadIdx.x) * 4;
    float4 v = *(const float4*)(in + i);
    *(hf2*)(hi + i)     = __floats2half2_rn(v.x, v.y);
    *(hf2*)(hi + i + 2) = __floats2half2_rn(v.z, v.w);
}

/* ---------------- theta + softmax -> fp16 (hi only) ----------------------- */
__global__ void __launch_bounds__(256) theta_softmax2048_hf(
    const float* __restrict__ S, hf* __restrict__ Phi)
{
    __shared__ float red[8];
    const float* row = S + (long long)blockIdx.x * 2048;
    long long ob = (long long)blockIdx.x * 2048;
    int tid = threadIdx.x;
    float4 v0 = ((const float4*)row)[tid];
    float4 v1 = ((const float4*)row)[tid + 256];
    v0.x = theta_fn(v0.x); v0.y = theta_fn(v0.y); v0.z = theta_fn(v0.z); v0.w = theta_fn(v0.w);
    v1.x = theta_fn(v1.x); v1.y = theta_fn(v1.y); v1.z = theta_fn(v1.z); v1.w = theta_fn(v1.w);
    float m = fmaxf(fmaxf(fmaxf(v0.x, v0.y), fmaxf(v0.z, v0.w)),
                    fmaxf(fmaxf(v1.x, v1.y), fmaxf(v1.z, v1.w)));
    #pragma unroll
    for (int o = 16; o; o >>= 1) m = fmaxf(m, __shfl_xor_sync(0xffffffffu, m, o));
    if ((tid & 31) == 0) red[tid >> 5] = m;
    __syncthreads();
    m = fmaxf(fmaxf(fmaxf(red[0], red[1]), fmaxf(red[2], red[3])),
              fmaxf(fmaxf(red[4], red[5]), fmaxf(red[6], red[7])));
    v0.x = __expf(v0.x - m); v0.y = __expf(v0.y - m); v0.z = __expf(v0.z - m); v0.w = __expf(v0.w - m);
    v1.x = __expf(v1.x - m); v1.y = __expf(v1.y - m); v1.z = __expf(v1.z - m); v1.w = __expf(v1.w - m);
    float s = v0.x + v0.y + v0.z + v0.w + v1.x + v1.y + v1.z + v1.w;
    #pragma unroll
    for (int o = 16; o; o >>= 1) s += __shfl_xor_sync(0xffffffffu, s, o);
    __syncthreads();
    if ((tid & 31) == 0) red[tid >> 5] = s;
    __syncthreads();
    s = red[0] + red[1] + red[2] + red[3] + red[4] + red[5] + red[6] + red[7];
    float r = 1.0f / s;
    v0.x *= r; v0.y *= r; v0.z *= r; v0.w *= r;
    v1.x *= r; v1.y *= r; v1.z *= r; v1.w *= r;
    *(hf2*)(Phi + ob + tid*4)            = __floats2half2_rn(v0.x, v0.y);
    *(hf2*)(Phi + ob + tid*4 + 2)        = __floats2half2_rn(v0.z, v0.w);
    *(hf2*)(Phi + ob + 1024 + tid*4)     = __floats2half2_rn(v1.x, v1.y);
    *(hf2*)(Phi + ob + 1024 + tid*4 + 2) = __floats2half2_rn(v1.z, v1.w);
}

/* ---------------- LayerNorm over 1024 -> fp16 ----------------------------- */
__global__ void __launch_bounds__(256) layernorm1024_hf(
    const float* __restrict__ X, const float* __restrict__ g,
    const float* __restrict__ bta, hf* __restrict__ Yhi)
{
    __shared__ float rs[8], rq[8];
    long long base = (long long)blockIdx.x * 1024;
    int tid = threadIdx.x;
    float4 v = *(const float4*)(X + base + tid * 4);
    float s = v.x + v.y + v.z + v.w;
    float q = v.x*v.x + v.y*v.y + v.z*v.z + v.w*v.w;
    #pragma unroll
    for (int o = 16; o; o >>= 1) {
        s += __shfl_xor_sync(0xffffffffu, s, o);
        q += __shfl_xor_sync(0xffffffffu, q, o);
    }
    if ((tid & 31) == 0) { rs[tid >> 5] = s; rq[tid >> 5] = q; }
    __syncthreads();
    s = rs[0] + rs[1] + rs[2] + rs[3] + rs[4] + rs[5] + rs[6] + rs[7];
    q = rq[0] + rq[1] + rq[2] + rq[3] + rq[4] + rq[5] + rq[6] + rq[7];
    float mu  = s * (1.0f / 1024.0f);
    float var = q * (1.0f / 1024.0f) - mu * mu;
    float inv = rsqrtf(var + 1e-5f);
    float4 gg = *(const float4*)(g + tid * 4);
    float4 bb = *(const float4*)(bta + tid * 4);
    float o0 = (v.x - mu) * inv * gg.x + bb.x;
    float o1 = (v.y - mu) * inv * gg.y + bb.y;
    float o2 = (v.z - mu) * inv * gg.z + bb.z;
    float o3 = (v.w - mu) * inv * gg.w + bb.w;
    *(hf2*)(Yhi + base + tid*4)     = __floats2half2_rn(o0, o1);
    *(hf2*)(Yhi + base + tid*4 + 2) = __floats2half2_rn(o2, o3);
}

/* ---------------- residual adds ------------------------------------------- */
__global__ void __launch_bounds__(256) add_hf(
    float* __restrict__ out, const float* __restrict__ a, const float* __restrict__ b,
    hf* __restrict__ hi)
{
    long long i = ((long long)blockIdx.x * 256 + threadIdx.x) * 4;
    float4 av = *(const float4*)(a + i);
    float4 bv = *(const float4*)(b + i);
    av.x += bv.x; av.y += bv.y; av.z += bv.z; av.w += bv.w;
    *(float4*)(out + i) = av;
    *(hf2*)(hi + i)     = __floats2half2_rn(av.x, av.y);
    *(hf2*)(hi + i + 2) = __floats2half2_rn(av.z, av.w);
}
__global__ void __launch_bounds__(256) add_plain(
    float* __restrict__ out, const float* __restrict__ b)
{
    long long i = ((long long)blockIdx.x * 256 + threadIdx.x) * 4;
    float4 av = *(const float4*)(out + i);
    float4 bv = *(const float4*)(b + i);
    av.x += bv.x; av.y += bv.y; av.z += bv.z; av.w += bv.w;
    *(float4*)(out + i) = av;
}

/* ---------------- host-side dispatch -------------------------------------- */
#define SMEM_G     148480   /* 3*(16384+32768) + 1024 */
#define SMEM_FLASH 132096   /* needs 115712; padded to pin 1 CTA/SM */

extern "C" void kernel_launch(void* const* d_in, const int* in_sizes, int n_in,
                              void* d_out, int out_size)
{
    const float* x     = (const float*)d_in[0];
    const float* ln1_g = (const float*)d_in[1];
    const float* ln1_b = (const float*)d_in[2];
    const float* qkv_w = (const float*)d_in[3];
    const float* qkv_b = (const float*)d_in[4];
    const float* proj_w= (const float*)d_in[5];
    const float* proj_b= (const float*)d_in[6];
    const float* kq_w  = (const float*)d_in[7];
    const float* kq_b  = (const float*)d_in[8];
    const float* kk_w  = (const float*)d_in[9];
    const float* kk_b  = (const float*)d_in[10];
    const float* kv_w  = (const float*)d_in[11];
    const float* kv_b  = (const float*)d_in[12];
    const float* ko_w  = (const float*)d_in[13];
    const float* ko_b  = (const float*)d_in[14];
    const float* ln2_g = (const float*)d_in[15];
    const float* ln2_b = (const float*)d_in[16];
    const float* fc1_w = (const float*)d_in[17];
    const float* fc1_b = (const float*)d_in[18];
    const float* fc2_w = (const float*)d_in[19];
    const float* fc2_b = (const float*)d_in[20];
    float* out = (float*)d_out;

    float *sc, *bufA;
    hf *whi, *lnhi, *qkvhi, *schi, *aohi, *reshi, *ffhi;
    cudaGetSymbolAddress((void**)&sc,    g_sc);
    cudaGetSymbolAddress((void**)&bufA,  g_bufA);
    cudaGetSymbolAddress((void**)&whi,   g_whi);
    cudaGetSymbolAddress((void**)&lnhi,  g_lnhi);
    cudaGetSymbolAddress((void**)&qkvhi, g_qkvhi);
    cudaGetSymbolAddress((void**)&schi,  g_schi);
    cudaGetSymbolAddress((void**)&aohi,  g_aohi);
    cudaGetSymbolAddress((void**)&reshi, g_reshi);
    cudaGetSymbolAddress((void**)&ffhi,  g_ffhi);

    cudaFuncSetAttribute(bgemm<256, false, false, 1>, cudaFuncAttributeMaxDynamicSharedMemorySize, SMEM_G);
    cudaFuncSetAttribute(bgemm<256, false, false, 0>, cudaFuncAttributeMaxDynamicSharedMemorySize, SMEM_G);
    cudaFuncSetAttribute(bgemm<256, false, true,  1>, cudaFuncAttributeMaxDynamicSharedMemorySize, SMEM_G);
    cudaFuncSetAttribute(bgemm<256, true,  false, 0>, cudaFuncAttributeMaxDynamicSharedMemorySize, SMEM_G);
    cudaFuncSetAttribute(flash_mha, cudaFuncAttributeMaxDynamicSharedMemorySize, SMEM_FLASH);

    const long long NN = (long long)NTOK * NTOK;
    const long long TC = (long long)NTOK * DIMC;
    const int nElemBlks = (TTOK * DIMC) / (4 * 256);
    dim3 tb(256);

    /* launches 1-5 (launch #6 = QKV GEMM for ncu -s 5 -c 1) */
    conv_vec<<<3072, tb>>>(qkv_w,  whi + W_QKV);
    conv_vec<<<1024, tb>>>(proj_w, whi + W_PROJ);
    conv_vec<<<1024, tb>>>(kq_w,   whi + W_KQ);
    conv_vec<<<1024, tb>>>(kk_w,   whi + W_KK);
    layernorm1024_hf<<<TTOK, tb>>>(x, ln1_g, ln1_b, lnhi);

    /* launch #6: qkv = ln1 @ qkv_w + b */
    bgemm<256, false, false, 1><<<dim3(12, 32, 1), tb, SMEM_G>>>(
        lnhi, whi + W_QKV, nullptr, qkvhi, qkv_b,
        1024, 1024, 3072, 3072, 1, 0,0, 0,0, 0,0, 1.0f);

    conv_vec<<<1024, tb>>>(kv_w,   whi + W_KV);
    conv_vec<<<1024, tb>>>(ko_w,   whi + W_KO);
    conv_vec<<<4096, tb>>>(fc1_w,  whi + W_FC1);
    conv_vec<<<4096, tb>>>(fc2_w,  whi + W_FC2);

    /* fused MHA attention -> aohi */
    flash_mha<<<dim3(16, 32), tb, SMEM_FLASH>>>(qkvhi, aohi);

    bgemm<256, false, false, 0><<<dim3(4, 32, 1), tb, SMEM_G>>>(
        aohi, whi + W_PROJ, bufA, nullptr, proj_b,
        1024, 1024, 1024, 1024, 1, 0,0, 0,0, 0,0, 1.0f);
    add_hf<<<nElemBlks, tb>>>(out, x, bufA, reshi);

    /* ---- sublayer 2: kernel attention (single-A throughout) ---- */
    hf* bqhi = qkvhi;
    hf* bkhi = qkvhi + (size_t)TTOK*DIMC;
    hf* bvhi = qkvhi + (size_t)2*TTOK*DIMC;

    bgemm<256, false, false, 1><<<dim3(4, 32, 1), tb, SMEM_G>>>(
        reshi, whi + W_KQ, nullptr, bqhi, kq_b,
        1024, 1024, 1024, 1024, 1, 0,0, 0,0, 0,0, 1.0f);
    bgemm<256, false, false, 1><<<dim3(4, 32, 1), tb, SMEM_G>>>(
        reshi, whi + W_KK, nullptr, bkhi, kk_b,
        1024, 1024, 1024, 1024, 1, 0,0, 0,0, 0,0, 1.0f);
    bgemm<256, false, false, 1><<<dim3(4, 32, 1), tb, SMEM_G>>>(
        reshi, whi + W_KV, nullptr, bvhi, kv_b,
        1024, 1024, 1024, 1024, 1, 0,0, 0,0, 0,0, 1.0f);

    /* qk = q @ k^T per batch (single-A TB, k-tile 64) */
    bgemm<256, true, false, 0><<<dim3(8, 16, BATCHN), tb, SMEM_G>>>(
        bqhi, bkhi, sc, nullptr, nullptr,
        1024, 1024, 1024, NTOK, 1, TC, 0, TC, 0, NN, 0, 1.0f);

    theta_softmax2048_hf<<<BATCHN*NTOK, tb>>>(sc, schi);

    /* av = attn @ v per batch (single-A NN, k-tile 64) */
    bgemm<256, false, false, 1><<<dim3(4, 16, BATCHN), tb, SMEM_G>>>(
        schi, bvhi, nullptr, aohi, nullptr,
        NTOK, NTOK, DIMC, DIMC, 1, NN, 0, TC, 0, TC, 0, 1.0f);

    bgemm<256, false, false, 0><<<dim3(4, 32, 1), tb, SMEM_G>>>(
        aohi, whi + W_KO, bufA, nullptr, ko_b,
        1024, 1024, 1024, 1024, 1, 0,0, 0,0, 0,0, 1.0f);
    add_plain<<<nElemBlks, tb>>>(out, bufA);

    /* ---- sublayer 3: FFN ---- */
    layernorm1024_hf<<<TTOK, tb>>>(out, ln2_g, ln2_b, lnhi);
    bgemm<256, false, true, 1><<<dim3(16, 32, 1), tb, SMEM_G>>>(
        lnhi, whi + W_FC1, nullptr, ffhi, fc1_b,
        1024, 1024, 4096, 4096, 1, 0,0, 0,0, 0,0, 1.0f);
    bgemm<256, false, false, 0><<<dim3(4, 32, 1), tb, SMEM_G>>>(
        ffhi, whi + W_FC2, bufA, nullptr, fc2_b,
        4096, 4096, 1024, 1024, 1, 0,0, 0,0, 0,0, 1.0f);
    add_plain<<<nElemBlks, tb>>>(out, bufA);
}

// round 15
// speedup vs baseline: 1.5255x; 1.0161x over previous
#include <cuda_runtime.h>
#include <cuda_fp16.h>
#include <math.h>

#define DIMC 1024
#define NTOK 2048
#define BATCHN 2
#define TTOK (BATCHN*NTOK)
#define NHEADS 16
#define HDIM 64
#define DFF 4096

typedef __half hf;
typedef __half2 hf2;

/* ---------------- scratch (device globals; no allocations allowed) -------- */
__device__ float g_sc  [(size_t)BATCHN*NTOK*NTOK];          /* 32 MB kernel-attn scores */
__device__ float g_bufA[(size_t)TTOK*DIMC];                 /* 16 MB fp32 */
__device__ float g_bias3[3072];
__device__ hf g_whi[16777216];
__device__ hf g_lnhi [(size_t)TTOK*DIMC];
__device__ hf g_qkvhi[(size_t)TTOK*3*DIMC];
__device__ hf g_schi [(size_t)BATCHN*NTOK*NTOK];
__device__ hf g_aohi [(size_t)TTOK*DIMC];
__device__ hf g_reshi[(size_t)TTOK*DIMC];
__device__ hf g_ffhi [(size_t)TTOK*DFF];

#define W_QKV  0LL
#define W_PROJ 3145728LL
#define W_KQKV 4194304LL   /* combined [1024, 3072] kq|kk|kv */
#define W_KO   7340032LL
#define W_FC1  8388608LL
#define W_FC2  12582912LL

/* ---------------- helpers ------------------------------------------------- */
__device__ __forceinline__ float gelu_f(float x) {
    return 0.5f * x * (1.0f + erff(x * 0.7071067811865476f));
}
__device__ __forceinline__ float theta_fn(float x) {
    float sg = 1.0f / (1.0f + __expf(-x));
    float rl = fmaxf(x, 0.0f);
    return 0.5f + 0.2f * sg + 0.15f * tanhf(x) + 0.1f * rl;
}
__device__ __forceinline__ void ldsm4(unsigned& r0, unsigned& r1, unsigned& r2, unsigned& r3, unsigned a) {
    asm volatile("ldmatrix.sync.aligned.m8n8.x4.shared.b16 {%0,%1,%2,%3}, [%4];"
                 : "=r"(r0), "=r"(r1), "=r"(r2), "=r"(r3) : "r"(a));
}
__device__ __forceinline__ void ldsm4t(unsigned& r0, unsigned& r1, unsigned& r2, unsigned& r3, unsigned a) {
    asm volatile("ldmatrix.sync.aligned.m8n8.x4.trans.shared.b16 {%0,%1,%2,%3}, [%4];"
                 : "=r"(r0), "=r"(r1), "=r"(r2), "=r"(r3) : "r"(a));
}
__device__ __forceinline__ void mma16816(float* d, const unsigned* a, const unsigned* b) {
    asm volatile(
        "mma.sync.aligned.m16n8k16.row.col.f32.f16.f16.f32 "
        "{%0,%1,%2,%3}, {%4,%5,%6,%7}, {%8,%9}, {%0,%1,%2,%3};"
        : "+f"(d[0]), "+f"(d[1]), "+f"(d[2]), "+f"(d[3])
        : "r"(a[0]), "r"(a[1]), "r"(a[2]), "r"(a[3]), "r"(b[0]), "r"(b[1]));
}
__device__ __forceinline__ void cpa16(unsigned dst, const void* src) {
    asm volatile("cp.async.cg.shared.global [%0], [%1], 16;" :: "r"(dst), "l"(src));
}
#define CP_COMMIT() asm volatile("cp.async.commit_group;")
#define CP_WAIT1()  asm volatile("cp.async.wait_group 1;")
#define CP_WAIT2()  asm volatile("cp.async.wait_group 2;")

/* ---------------- fp16 tensor-core GEMM (cp.async 3-stage, k-tile 64) -----
   C[z] = alpha * A[z](M x K) * op(B[z]) + bias ; op = B [K,N] (NN) or B^T (TB)
   A, B single RN fp16. OUTM: 0 = fp32 C, 1 = fp16 Chi.
   M%128==0, N%256==0 (NTILE=256), K%64==0.                                 */
template<int NTILE, bool TB, bool GELU, int OUTM>
__global__ void __launch_bounds__(256, 1) bgemm(
    const hf* __restrict__ Ahi, const hf* __restrict__ Bhi,
    float* __restrict__ C, hf* __restrict__ Chi,
    const float* __restrict__ bias,
    int K, int lda, int ldb, int ldc, int zdiv,
    long long sA1, long long sA2, long long sB1, long long sB2,
    long long sC1, long long sC2, float alpha)
{
    extern __shared__ char dsm[];
    constexpr int KT     = 64;
    constexpr int ABYTES = 16384;            /* 128 rows x 128B */
    constexpr int BBYTES = NTILE * 128;      /* TB: NTILE rows x 128B ; NN: 64 rows x NTILE*2 */
    constexpr int STAGE  = ABYTES + BBYTES;

    unsigned smRaw  = (unsigned)__cvta_generic_to_shared(dsm);
    unsigned smBase = (smRaw + 1023u) & ~1023u;

    int z = blockIdx.z, z1 = z / zdiv, z2 = z % zdiv;
    const hf* Ah = Ahi + z1 * sA1 + z2 * sA2;
    const hf* Bh = Bhi + z1 * sB1 + z2 * sB2;
    long long coff = z1 * sC1 + z2 * sC2;

    int rowBase = blockIdx.y * 128;
    int colBase = blockIdx.x * NTILE;
    int tid = threadIdx.x, lane = tid & 31, w = tid >> 5;

    constexpr int MF = 4;                 /* warp tile 64 x (NTILE/4) */
    constexpr int NF = NTILE / 32;        /* 8 */
    int warpRow = (w & 1) * 64;
    int warpCol = (w >> 1) * (NTILE / 4);

    float acc[MF][NF][4] = {};

    auto issue = [&](int s, int k0) {
        unsigned sA = smBase + s * STAGE;
        unsigned sB = sA + ABYTES;
        #pragma unroll
        for (int i = 0; i < 4; i++) {
            int li = tid + i * 256, r = li >> 3, ch = li & 7;
            const hf* src = Ah + (long long)(rowBase + r) * lda + k0 + ch * 8;
            cpa16(sA + r * 128 + ((ch ^ (r & 7)) << 4), src);
        }
        if (TB) {
            #pragma unroll
            for (int i = 0; i < NTILE / 32; i++) {
                int li = tid + i * 256, r = li >> 3, ch = li & 7;
                const hf* src = Bh + (long long)(colBase + r) * ldb + k0 + ch * 8;
                cpa16(sB + r * 128 + ((ch ^ (r & 7)) << 4), src);
            }
        } else {
            constexpr int CPR = NTILE / 8;            /* 16B chunks per B row */
            #pragma unroll
            for (int i = 0; i < (64 * CPR) / 256; i++) {
                int li = tid + i * 256;
                int r = li / CPR, ch = li % CPR;
                const hf* src = Bh + (long long)(k0 + r) * ldb + colBase + ch * 8;
                cpa16(sB + r * (NTILE * 2) + ((ch ^ (r & 7)) << 4), src);
            }
        }
    };

    auto compute = [&](int s) {
        unsigned sA = smBase + s * STAGE;
        unsigned sB = sA + ABYTES;
        #pragma unroll
        for (int ks = 0; ks < 4; ks++) {
            unsigned ah[MF][4];
            #pragma unroll
            for (int mf = 0; mf < MF; mf++) {
                int ar = warpRow + mf * 16 + (lane & 15);
                int ac = ks * 2 + (lane >> 4);
                ldsm4(ah[mf][0], ah[mf][1], ah[mf][2], ah[mf][3],
                      sA + ar * 128 + ((ac ^ (ar & 7)) << 4));
            }
            #pragma unroll
            for (int np = 0; np < NF / 2; np++) {
                unsigned bh[2][2];
                if (!TB) {
                    int bk = ks * 16 + (lane & 15);
                    int nc = (warpCol + np * 16 + ((lane >> 4) << 3)) >> 3;
                    ldsm4t(bh[0][0], bh[0][1], bh[1][0], bh[1][1],
                           sB + bk * (NTILE * 2) + ((nc ^ (bk & 7)) << 4));
                } else {
                    int br = warpCol + np * 16 + ((lane >> 4) << 3) + (lane & 7);
                    int kc = ks * 2 + ((lane >> 3) & 1);
                    ldsm4(bh[0][0], bh[0][1], bh[1][0], bh[1][1],
                          sB + br * 128 + ((kc ^ (br & 7)) << 4));
                }
                #pragma unroll
                for (int mf = 0; mf < MF; mf++)
                    #pragma unroll
                    for (int j = 0; j < 2; j++) mma16816(acc[mf][2*np+j], ah[mf], bh[j]);
            }
        }
    };

    int nk = K / KT;
    issue(0, 0); CP_COMMIT();
    if (nk > 1) issue(1, KT);
    CP_COMMIT();
    for (int i = 0; i < nk; i++) {
        CP_WAIT1();
        __syncthreads();
        if (i + 2 < nk) issue((i + 2) % 3, (i + 2) * KT);
        CP_COMMIT();
        compute(i % 3);
    }

    #pragma unroll
    for (int mf = 0; mf < MF; mf++) {
        #pragma unroll
        for (int nf = 0; nf < NF; nf++) {
            int row = rowBase + warpRow + mf * 16 + (lane >> 2);
            int col = colBase + warpCol + nf * 8 + (lane & 3) * 2;
            float bx = 0.f, by = 0.f;
            if (bias) { float2 bb = *(const float2*)(bias + col); bx = bb.x; by = bb.y; }
            float v0 = acc[mf][nf][0] * alpha + bx;
            float v1 = acc[mf][nf][1] * alpha + by;
            float v2 = acc[mf][nf][2] * alpha + bx;
            float v3 = acc[mf][nf][3] * alpha + by;
            if (GELU) { v0 = gelu_f(v0); v1 = gelu_f(v1); v2 = gelu_f(v2); v3 = gelu_f(v3); }
            long long o0 = coff + (long long)row * ldc + col;
            long long o1 = coff + (long long)(row + 8) * ldc + col;
            if (OUTM == 0) {
                *(float2*)(C + o0) = make_float2(v0, v1);
                *(float2*)(C + o1) = make_float2(v2, v3);
            } else {
                *(hf2*)(Chi + o0) = __floats2half2_rn(v0, v1);
                *(hf2*)(Chi + o1) = __floats2half2_rn(v2, v3);
            }
        }
    }
}

/* ---------------- fused flash MHA (QK^T + softmax + PV), single fp16 ------
   Smem request padded to 132096 to pin 1 CTA/SM (R12-verified).            */
__global__ void __launch_bounds__(256, 1) flash_mha(
    const hf* __restrict__ QKVhi, hf* __restrict__ Ohi)
{
    extern __shared__ char dsm[];
    unsigned smRaw = (unsigned)__cvta_generic_to_shared(dsm);
    unsigned smQ  = (smRaw + 1023u) & ~1023u;    /* 16K */
    unsigned smKV = smQ + 16384;                 /* 3 stages x [KH 16K | VH 16K] */

    int bh = blockIdx.y;
    int b = bh >> 4, h = bh & 15;
    long long rowBase = (long long)b * NTOK;
    int qRow0 = blockIdx.x * 128;
    const int ld = 3 * DIMC;
    int qcol = h * 64, kcol = DIMC + h * 64, vcol = 2 * DIMC + h * 64;

    int tid = threadIdx.x, lane = tid & 31, w = tid >> 5;

    #pragma unroll
    for (int i = 0; i < 4; i++) {
        int li = tid + i * 256, r = li >> 3, ch = li & 7;
        unsigned sw = r * 128 + ((ch ^ (r & 7)) << 4);
        cpa16(smQ + sw, QKVhi + (rowBase + qRow0 + r) * ld + qcol + ch * 8);
    }
    CP_COMMIT();

    auto issueKV = [&](int s, int kt0) {
        unsigned base = smKV + s * 32768;
        #pragma unroll
        for (int i = 0; i < 4; i++) {
            int li = tid + i * 256, r = li >> 3, ch = li & 7;
            unsigned sw = r * 128 + ((ch ^ (r & 7)) << 4);
            long long g = (rowBase + kt0 + r) * ld;
            cpa16(base + sw,         QKVhi + g + kcol + ch * 8);
            cpa16(base + 16384 + sw, QKVhi + g + vcol + ch * 8);
        }
    };

    issueKV(0, 0);   CP_COMMIT();
    issueKV(1, 128); CP_COMMIT();

    CP_WAIT2();
    __syncthreads();

    unsigned qh[4][4];
    {
        int ar = w * 16 + (lane & 15);
        hf2 s2 = __floats2half2_rn(0.125f, 0.125f);
        #pragma unroll
        for (int c = 0; c < 4; c++) {
            int ac = c * 2 + (lane >> 4);
            ldsm4(qh[c][0], qh[c][1], qh[c][2], qh[c][3],
                  smQ + ar * 128 + ((ac ^ (ar & 7)) << 4));
            #pragma unroll
            for (int r = 0; r < 4; r++) {
                hf2 t = *(hf2*)&qh[c][r]; t = __hmul2(t, s2); qh[c][r] = *(unsigned*)&t;
            }
        }
    }

    float o[8][4] = {};
    float l0 = 0.f, l1 = 0.f;

    for (int kt = 0; kt < 16; kt++) {
        CP_WAIT1();
        __syncthreads();
        if (kt + 2 < 16) issueKV((kt + 2) % 3, (kt + 2) * 128);
        CP_COMMIT();

        unsigned base = smKV + (kt % 3) * 32768;

        float sacc[16][4] = {};
        #pragma unroll
        for (int c = 0; c < 4; c++) {
            #pragma unroll
            for (int np = 0; np < 8; np++) {
                unsigned kh2[2][2];
                int br = np * 16 + ((lane >> 4) << 3) + (lane & 7);
                int kc = c * 2 + ((lane >> 3) & 1);
                ldsm4(kh2[0][0], kh2[0][1], kh2[1][0], kh2[1][1],
                      base + br * 128 + ((kc ^ (br & 7)) << 4));
                #pragma unroll
                for (int j = 0; j < 2; j++) mma16816(sacc[2*np+j], qh[c], kh2[j]);
            }
        }

        unsigned ph[8][4];
        #pragma unroll
        for (int f = 0; f < 16; f++) {
            float p0 = __expf(sacc[f][0]);
            float p1 = __expf(sacc[f][1]);
            float p2 = __expf(sacc[f][2]);
            float p3 = __expf(sacc[f][3]);
            l0 += p0 + p1;
            l1 += p2 + p3;
            int j = f >> 1, hfi = f & 1;
            hf2 a = __floats2half2_rn(p0, p1);
            hf2 c = __floats2half2_rn(p2, p3);
            ph[j][hfi*2+0] = *(unsigned*)&a;
            ph[j][hfi*2+1] = *(unsigned*)&c;
        }

        unsigned vb = base + 16384;
        #pragma unroll
        for (int j = 0; j < 8; j++) {
            #pragma unroll
            for (int np2 = 0; np2 < 4; np2++) {
                unsigned vh[2][2];
                int bk = j * 16 + (lane & 15);
                int nc = (np2 * 16 + ((lane >> 4) << 3)) >> 3;
                ldsm4t(vh[0][0], vh[0][1], vh[1][0], vh[1][1],
                       vb + bk * 128 + ((nc ^ (bk & 7)) << 4));
                #pragma unroll
                for (int t = 0; t < 2; t++) mma16816(o[2*np2+t], ph[j], vh[t]);
            }
        }
    }

    l0 += __shfl_xor_sync(0xffffffffu, l0, 1);
    l0 += __shfl_xor_sync(0xffffffffu, l0, 2);
    l1 += __shfl_xor_sync(0xffffffffu, l1, 1);
    l1 += __shfl_xor_sync(0xffffffffu, l1, 2);
    float i0 = 1.0f / l0, i1 = 1.0f / l1;

    long long or0 = (rowBase + qRow0 + w * 16 + (lane >> 2)) * DIMC + h * 64;
    #pragma unroll
    for (int nf = 0; nf < 8; nf++) {
        int col = nf * 8 + (lane & 3) * 2;
        *(hf2*)(Ohi + or0 + col)            = __floats2half2_rn(o[nf][0] * i0, o[nf][1] * i0);
        *(hf2*)(Ohi + or0 + 8 * DIMC + col) = __floats2half2_rn(o[nf][2] * i1, o[nf][3] * i1);
    }
}

/* ---------------- merged weight convert: all 8 weights, one launch --------
   grid 16384 x 256 threads, 1024 fp32 elems per block.
   kq/kk/kv are interleaved into a combined [1024, 3072] at W_KQKV.        */
__global__ void __launch_bounds__(256) conv_all(
    const float* __restrict__ qkv_w, const float* __restrict__ proj_w,
    const float* __restrict__ kq_w,  const float* __restrict__ kk_w,
    const float* __restrict__ kv_w,  const float* __restrict__ ko_w,
    const float* __restrict__ fc1_w, const float* __restrict__ fc2_w,
    hf* __restrict__ whi)
{
    int blk = blockIdx.x, tid = threadIdx.x;
    const float* src;
    hf* dst;
    if (blk < 3072)      { src = qkv_w  + (long long)blk * 1024; dst = whi + W_QKV  + (long long)blk * 1024; }
    else if (blk < 4096) { src = proj_w + (long long)(blk - 3072) * 1024; dst = whi + W_PROJ + (long long)(blk - 3072) * 1024; }
    else if (blk < 5120) { int r = blk - 4096; src = kq_w + (long long)r * 1024; dst = whi + W_KQKV + (long long)r * 3072; }
    else if (blk < 6144) { int r = blk - 5120; src = kk_w + (long long)r * 1024; dst = whi + W_KQKV + (long long)r * 3072 + 1024; }
    else if (blk < 7168) { int r = blk - 6144; src = kv_w + (long long)r * 1024; dst = whi + W_KQKV + (long long)r * 3072 + 2048; }
    else if (blk < 8192) { src = ko_w  + (long long)(blk - 7168) * 1024; dst = whi + W_KO  + (long long)(blk - 7168) * 1024; }
    else if (blk < 12288){ src = fc1_w + (long long)(blk - 8192) * 1024; dst = whi + W_FC1 + (long long)(blk - 8192) * 1024; }
    else                 { src = fc2_w + (long long)(blk - 12288) * 1024; dst = whi + W_FC2 + (long long)(blk - 12288) * 1024; }
    float4 v = *(const float4*)(src + tid * 4);
    *(hf2*)(dst + tid * 4)     = __floats2half2_rn(v.x, v.y);
    *(hf2*)(dst + tid * 4 + 2) = __floats2half2_rn(v.z, v.w);
}

__global__ void __launch_bounds__(256) concat_bias(
    const float* __restrict__ a, const float* __restrict__ b,
    const float* __restrict__ c, float* __restrict__ o)
{
    int i = blockIdx.x * 256 + threadIdx.x;
    o[i] = (i < 1024) ? a[i] : ((i < 2048) ? b[i - 1024] : c[i - 2048]);
}

/* ---------------- theta + softmax -> fp16 (hi only) ----------------------- */
__global__ void __launch_bounds__(256) theta_softmax2048_hf(
    const float* __restrict__ S, hf* __restrict__ Phi)
{
    __shared__ float red[8];
    const float* row = S + (long long)blockIdx.x * 2048;
    long long ob = (long long)blockIdx.x * 2048;
    int tid = threadIdx.x;
    float4 v0 = ((const float4*)row)[tid];
    float4 v1 = ((const float4*)row)[tid + 256];
    v0.x = theta_fn(v0.x); v0.y = theta_fn(v0.y); v0.z = theta_fn(v0.z); v0.w = theta_fn(v0.w);
    v1.x = theta_fn(v1.x); v1.y = theta_fn(v1.y); v1.z = theta_fn(v1.z); v1.w = theta_fn(v1.w);
    float m = fmaxf(fmaxf(fmaxf(v0.x, v0.y), fmaxf(v0.z, v0.w)),
                    fmaxf(fmaxf(v1.x, v1.y), fmaxf(v1.z, v1.w)));
    #pragma unroll
    for (int o = 16; o; o >>= 1) m = fmaxf(m, __shfl_xor_sync(0xffffffffu, m, o));
    if ((tid & 31) == 0) red[tid >> 5] = m;
    __syncthreads();
    m = fmaxf(fmaxf(fmaxf(red[0], red[1]), fmaxf(red[2], red[3])),
              fmaxf(fmaxf(red[4], red[5]), fmaxf(red[6], red[7])));
    v0.x = __expf(v0.x - m); v0.y = __expf(v0.y - m); v0.z = __expf(v0.z - m); v0.w = __expf(v0.w - m);
    v1.x = __expf(v1.x - m); v1.y = __expf(v1.y - m); v1.z = __expf(v1.z - m); v1.w = __expf(v1.w - m);
    float s = v0.x + v0.y + v0.z + v0.w + v1.x + v1.y + v1.z + v1.w;
    #pragma unroll
    for (int o = 16; o; o >>= 1) s += __shfl_xor_sync(0xffffffffu, s, o);
    __syncthreads();
    if ((tid & 31) == 0) red[tid >> 5] = s;
    __syncthreads();
    s = red[0] + red[1] + red[2] + red[3] + red[4] + red[5] + red[6] + red[7];
    float r = 1.0f / s;
    v0.x *= r; v0.y *= r; v0.z *= r; v0.w *= r;
    v1.x *= r; v1.y *= r; v1.z *= r; v1.w *= r;
    *(hf2*)(Phi + ob + tid*4)            = __floats2half2_rn(v0.x, v0.y);
    *(hf2*)(Phi + ob + tid*4 + 2)        = __floats2half2_rn(v0.z, v0.w);
    *(hf2*)(Phi + ob + 1024 + tid*4)     = __floats2half2_rn(v1.x, v1.y);
    *(hf2*)(Phi + ob + 1024 + tid*4 + 2) = __floats2half2_rn(v1.z, v1.w);
}

/* ---------------- LayerNorm over 1024 -> fp16 ----------------------------- */
__global__ void __launch_bounds__(256) layernorm1024_hf(
    const float* __restrict__ X, const float* __restrict__ g,
    const float* __restrict__ bta, hf* __restrict__ Yhi)
{
    __shared__ float rs[8], rq[8];
    long long base = (long long)blockIdx.x * 1024;
    int tid = threadIdx.x;
    float4 v = *(const float4*)(X + base + tid * 4);
    float s = v.x + v.y + v.z + v.w;
    float q = v.x*v.x + v.y*v.y + v.z*v.z + v.w*v.w;
    #pragma unroll
    for (int o = 16; o; o >>= 1) {
        s += __shfl_xor_sync(0xffffffffu, s, o);
        q += __shfl_xor_sync(0xffffffffu, q, o);
    }
    if ((tid & 31) == 0) { rs[tid >> 5] = s; rq[tid >> 5] = q; }
    __syncthreads();
    s = rs[0] + rs[1] + rs[2] + rs[3] + rs[4] + rs[5] + rs[6] + rs[7];
    q = rq[0] + rq[1] + rq[2] + rq[3] + rq[4] + rq[5] + rq[6] + rq[7];
    float mu  = s * (1.0f / 1024.0f);
    float var = q * (1.0f / 1024.0f) - mu * mu;
    float inv = rsqrtf(var + 1e-5f);
    float4 gg = *(const float4*)(g + tid * 4);
    float4 bb = *(const float4*)(bta + tid * 4);
    float o0 = (v.x - mu) * inv * gg.x + bb.x;
    float o1 = (v.y - mu) * inv * gg.y + bb.y;
    float o2 = (v.z - mu) * inv * gg.z + bb.z;
    float o3 = (v.w - mu) * inv * gg.w + bb.w;
    *(hf2*)(Yhi + base + tid*4)     = __floats2half2_rn(o0, o1);
    *(hf2*)(Yhi + base + tid*4 + 2) = __floats2half2_rn(o2, o3);
}

/* ---------------- residual adds ------------------------------------------- */
__global__ void __launch_bounds__(256) add_hf(
    float* __restrict__ out, const float* __restrict__ a, const float* __restrict__ b,
    hf* __restrict__ hi)
{
    long long i = ((long long)blockIdx.x * 256 + threadIdx.x) * 4;
    float4 av = *(const float4*)(a + i);
    float4 bv = *(const float4*)(b + i);
    av.x += bv.x; av.y += bv.y; av.z += bv.z; av.w += bv.w;
    *(float4*)(out + i) = av;
    *(hf2*)(hi + i)     = __floats2half2_rn(av.x, av.y);
    *(hf2*)(hi + i + 2) = __floats2half2_rn(av.z, av.w);
}
__global__ void __launch_bounds__(256) add_plain(
    float* __restrict__ out, const float* __restrict__ b)
{
    long long i = ((long long)blockIdx.x * 256 + threadIdx.x) * 4;
    float4 av = *(const float4*)(out + i);
    float4 bv = *(const float4*)(b + i);
    av.x += bv.x; av.y += bv.y; av.z += bv.z; av.w += bv.w;
    *(float4*)(out + i) = av;
}

/* ---------------- host-side dispatch -------------------------------------- */
#define SMEM_G     148480   /* 3*(16384+32768) + 1024 */
#define SMEM_FLASH 132096   /* needs 115712; padded to pin 1 CTA/SM */

extern "C" void kernel_launch(void* const* d_in, const int* in_sizes, int n_in,
                              void* d_out, int out_size)
{
    const float* x     = (const float*)d_in[0];
    const float* ln1_g = (const float*)d_in[1];
    const float* ln1_b = (const float*)d_in[2];
    const float* qkv_w = (const float*)d_in[3];
    const float* qkv_b = (const float*)d_in[4];
    const float* proj_w= (const float*)d_in[5];
    const float* proj_b= (const float*)d_in[6];
    const float* kq_w  = (const float*)d_in[7];
    const float* kq_b  = (const float*)d_in[8];
    const float* kk_w  = (const float*)d_in[9];
    const float* kk_b  = (const float*)d_in[10];
    const float* kv_w  = (const float*)d_in[11];
    const float* kv_b  = (const float*)d_in[12];
    const float* ko_w  = (const float*)d_in[13];
    const float* ko_b  = (const float*)d_in[14];
    const float* ln2_g = (const float*)d_in[15];
    const float* ln2_b = (const float*)d_in[16];
    const float* fc1_w = (const float*)d_in[17];
    const float* fc1_b = (const float*)d_in[18];
    const float* fc2_w = (const float*)d_in[19];
    const float* fc2_b = (const float*)d_in[20];
    float* out = (float*)d_out;

    float *sc, *bufA, *bias3;
    hf *whi, *lnhi, *qkvhi, *schi, *aohi, *reshi, *ffhi;
    cudaGetSymbolAddress((void**)&sc,    g_sc);
    cudaGetSymbolAddress((void**)&bufA,  g_bufA);
    cudaGetSymbolAddress((void**)&bias3, g_bias3);
    cudaGetSymbolAddress((void**)&whi,   g_whi);
    cudaGetSymbolAddress((void**)&lnhi,  g_lnhi);
    cudaGetSymbolAddress((void**)&qkvhi, g_qkvhi);
    cudaGetSymbolAddress((void**)&schi,  g_schi);
    cudaGetSymbolAddress((void**)&aohi,  g_aohi);
    cudaGetSymbolAddress((void**)&reshi, g_reshi);
    cudaGetSymbolAddress((void**)&ffhi,  g_ffhi);

    cudaFuncSetAttribute(bgemm<256, false, false, 1>, cudaFuncAttributeMaxDynamicSharedMemorySize, SMEM_G);
    cudaFuncSetAttribute(bgemm<256, false, false, 0>, cudaFuncAttributeMaxDynamicSharedMemorySize, SMEM_G);
    cudaFuncSetAttribute(bgemm<256, false, true,  1>, cudaFuncAttributeMaxDynamicSharedMemorySize, SMEM_G);
    cudaFuncSetAttribute(bgemm<256, true,  false, 0>, cudaFuncAttributeMaxDynamicSharedMemorySize, SMEM_G);
    cudaFuncSetAttribute(flash_mha, cudaFuncAttributeMaxDynamicSharedMemorySize, SMEM_FLASH);

    const long long NN = (long long)NTOK * NTOK;
    const long long TC = (long long)NTOK * DIMC;
    const int nElemBlks = (TTOK * DIMC) / (4 * 256);
    dim3 tb(256);

    /* weight conversion: one launch for all 8 matrices */
    conv_all<<<16384, tb>>>(qkv_w, proj_w, kq_w, kk_w, kv_w, ko_w, fc1_w, fc2_w, whi);
    concat_bias<<<12, tb>>>(kq_b, kk_b, kv_b, bias3);
    layernorm1024_hf<<<TTOK, tb>>>(x, ln1_g, ln1_b, lnhi);

    /* qkv = ln1 @ qkv_w + b */
    bgemm<256, false, false, 1><<<dim3(12, 32, 1), tb, SMEM_G>>>(
        lnhi, whi + W_QKV, nullptr, qkvhi, qkv_b,
        1024, 1024, 3072, 3072, 1, 0,0, 0,0, 0,0, 1.0f);

    /* fused MHA attention -> aohi */
    flash_mha<<<dim3(16, 32), tb, SMEM_FLASH>>>(qkvhi, aohi);

    bgemm<256, false, false, 0><<<dim3(4, 32, 1), tb, SMEM_G>>>(
        aohi, whi + W_PROJ, bufA, nullptr, proj_b,
        1024, 1024, 1024, 1024, 1, 0,0, 0,0, 0,0, 1.0f);
    add_hf<<<nElemBlks, tb>>>(out, x, bufA, reshi);

    /* ---- sublayer 2: kernel attention ---- */
    /* merged q|k|v = res @ [kq|kk|kv] + [biases] -> qkvhi [T, 3072] */
    bgemm<256, false, false, 1><<<dim3(12, 32, 1), tb, SMEM_G>>>(
        reshi, whi + W_KQKV, nullptr, qkvhi, bias3,
        1024, 1024, 3072, 3072, 1, 0,0, 0,0, 0,0, 1.0f);

    hf* bqhi = qkvhi;
    hf* bkhi = qkvhi + DIMC;
    hf* bvhi = qkvhi + 2 * DIMC;

    /* qk = q @ k^T per batch (single-A TB, k-tile 64, ld 3072) */
    bgemm<256, true, false, 0><<<dim3(8, 16, BATCHN), tb, SMEM_G>>>(
        bqhi, bkhi, sc, nullptr, nullptr,
        1024, 3072, 3072, NTOK, 1,
        (long long)NTOK*3*DIMC, 0, (long long)NTOK*3*DIMC, 0, NN, 0, 1.0f);

    theta_softmax2048_hf<<<BATCHN*NTOK, tb>>>(sc, schi);

    /* av = attn @ v per batch (single-A NN, ldb 3072) */
    bgemm<256, false, false, 1><<<dim3(4, 16, BATCHN), tb, SMEM_G>>>(
        schi, bvhi, nullptr, aohi, nullptr,
        NTOK, NTOK, 3*DIMC, DIMC, 1,
        NN, 0, (long long)NTOK*3*DIMC, 0, TC, 0, 1.0f);

    bgemm<256, false, false, 0><<<dim3(4, 32, 1), tb, SMEM_G>>>(
        aohi, whi + W_KO, bufA, nullptr, ko_b,
        1024, 1024, 1024, 1024, 1, 0,0, 0,0, 0,0, 1.0f);
    add_plain<<<nElemBlks, tb>>>(out, bufA);

    /* ---- sublayer 3: FFN ---- */
    layernorm1024_hf<<<TTOK, tb>>>(out, ln2_g, ln2_b, lnhi);
    bgemm<256, false, true, 1><<<dim3(16, 32, 1), tb, SMEM_G>>>(
        lnhi, whi + W_FC1, nullptr, ffhi, fc1_b,
        1024, 1024, 4096, 4096, 1, 0,0, 0,0, 0,0, 1.0f);
    bgemm<256, false, false, 0><<<dim3(4, 32, 1), tb, SMEM_G>>>(
        ffhi, whi + W_FC2, bufA, nullptr, fc2_b,
        4096, 4096, 1024, 1024, 1, 0,0, 0,0, 0,0, 1.0f);
    add_plain<<<nElemBlks, tb>>>(out, bufA);
}

// round 16
// speedup vs baseline: 1.5929x; 1.0441x over previous
#include <cuda_runtime.h>
#include <cuda_fp16.h>
#include <math.h>

#define DIMC 1024
#define NTOK 2048
#define BATCHN 2
#define TTOK (BATCHN*NTOK)
#define NHEADS 16
#define HDIM 64
#define DFF 4096

typedef __half hf;
typedef __half2 hf2;

/* ---------------- scratch (device globals; no allocations allowed) -------- */
__device__ float g_sc  [(size_t)BATCHN*NTOK*NTOK];          /* 32 MB kernel-attn scores */
__device__ float g_bufA[(size_t)TTOK*DIMC];                 /* 16 MB fp32 */
__device__ float g_bias3[3072];
__device__ hf g_whi[16777216];
__device__ hf g_lnhi [(size_t)TTOK*DIMC];
__device__ hf g_qkvhi[(size_t)TTOK*3*DIMC];
__device__ hf g_schi [(size_t)BATCHN*NTOK*NTOK];
__device__ hf g_aohi [(size_t)TTOK*DIMC];
__device__ hf g_reshi[(size_t)TTOK*DIMC];
__device__ hf g_ffhi [(size_t)TTOK*DFF];

#define W_QKV  0LL
#define W_PROJ 3145728LL
#define W_KQKV 4194304LL   /* combined [1024, 3072] kq|kk|kv */
#define W_KO   7340032LL
#define W_FC1  8388608LL
#define W_FC2  12582912LL

/* ---------------- helpers ------------------------------------------------- */
__device__ __forceinline__ float gelu_f(float x) {
    return 0.5f * x * (1.0f + erff(x * 0.7071067811865476f));
}
__device__ __forceinline__ float theta_fn(float x) {
    float sg = 1.0f / (1.0f + __expf(-x));
    float rl = fmaxf(x, 0.0f);
    return 0.5f + 0.2f * sg + 0.15f * tanhf(x) + 0.1f * rl;
}
__device__ __forceinline__ void ldsm4(unsigned& r0, unsigned& r1, unsigned& r2, unsigned& r3, unsigned a) {
    asm volatile("ldmatrix.sync.aligned.m8n8.x4.shared.b16 {%0,%1,%2,%3}, [%4];"
                 : "=r"(r0), "=r"(r1), "=r"(r2), "=r"(r3) : "r"(a));
}
__device__ __forceinline__ void ldsm4t(unsigned& r0, unsigned& r1, unsigned& r2, unsigned& r3, unsigned a) {
    asm volatile("ldmatrix.sync.aligned.m8n8.x4.trans.shared.b16 {%0,%1,%2,%3}, [%4];"
                 : "=r"(r0), "=r"(r1), "=r"(r2), "=r"(r3) : "r"(a));
}
__device__ __forceinline__ void mma16816(float* d, const unsigned* a, const unsigned* b) {
    asm volatile(
        "mma.sync.aligned.m16n8k16.row.col.f32.f16.f16.f32 "
        "{%0,%1,%2,%3}, {%4,%5,%6,%7}, {%8,%9}, {%0,%1,%2,%3};"
        : "+f"(d[0]), "+f"(d[1]), "+f"(d[2]), "+f"(d[3])
        : "r"(a[0]), "r"(a[1]), "r"(a[2]), "r"(a[3]), "r"(b[0]), "r"(b[1]));
}
__device__ __forceinline__ void cpa16(unsigned dst, const void* src) {
    asm volatile("cp.async.cg.shared.global [%0], [%1], 16;" :: "r"(dst), "l"(src));
}
#define CP_COMMIT() asm volatile("cp.async.commit_group;")
#define CP_WAIT1()  asm volatile("cp.async.wait_group 1;")
#define CP_WAIT2()  asm volatile("cp.async.wait_group 2;")

/* ---------------- fp16 tensor-core GEMM (cp.async 3-stage, k-tile 64) -----
   C[z] = alpha * A[z](M x K) * op(B[z]) + bias ; op = B [K,N] (NN) or B^T (TB)
   A, B single RN fp16. OUTM: 0 = fp32 C, 1 = fp16 Chi.
   NTILE=128, warp tile 64x32, 2 CTAs/SM (reg cap 128 via launch_bounds).
   M%128==0, N%128==0, K%64==0.                                             */
template<int NTILE, bool TB, bool GELU, int OUTM>
__global__ void __launch_bounds__(256, 2) bgemm(
    const hf* __restrict__ Ahi, const hf* __restrict__ Bhi,
    float* __restrict__ C, hf* __restrict__ Chi,
    const float* __restrict__ bias,
    int K, int lda, int ldb, int ldc, int zdiv,
    long long sA1, long long sA2, long long sB1, long long sB2,
    long long sC1, long long sC2, float alpha)
{
    extern __shared__ char dsm[];
    constexpr int KT     = 64;
    constexpr int ABYTES = 16384;            /* 128 rows x 128B */
    constexpr int BBYTES = NTILE * 128;      /* TB: NTILE rows x 128B ; NN: 64 rows x NTILE*2 */
    constexpr int STAGE  = ABYTES + BBYTES;

    unsigned smRaw  = (unsigned)__cvta_generic_to_shared(dsm);
    unsigned smBase = (smRaw + 1023u) & ~1023u;

    int z = blockIdx.z, z1 = z / zdiv, z2 = z % zdiv;
    const hf* Ah = Ahi + z1 * sA1 + z2 * sA2;
    const hf* Bh = Bhi + z1 * sB1 + z2 * sB2;
    long long coff = z1 * sC1 + z2 * sC2;

    int rowBase = blockIdx.y * 128;
    int colBase = blockIdx.x * NTILE;
    int tid = threadIdx.x, lane = tid & 31, w = tid >> 5;

    constexpr int MF = 4;                 /* warp tile 64 x (NTILE/4) */
    constexpr int NF = NTILE / 32;        /* 4 for NTILE=128 */
    int warpRow = (w & 1) * 64;
    int warpCol = (w >> 1) * (NTILE / 4);

    float acc[MF][NF][4] = {};

    auto issue = [&](int s, int k0) {
        unsigned sA = smBase + s * STAGE;
        unsigned sB = sA + ABYTES;
        #pragma unroll
        for (int i = 0; i < 4; i++) {
            int li = tid + i * 256, r = li >> 3, ch = li & 7;
            const hf* src = Ah + (long long)(rowBase + r) * lda + k0 + ch * 8;
            cpa16(sA + r * 128 + ((ch ^ (r & 7)) << 4), src);
        }
        if (TB) {
            #pragma unroll
            for (int i = 0; i < NTILE / 32; i++) {
                int li = tid + i * 256, r = li >> 3, ch = li & 7;
                const hf* src = Bh + (long long)(colBase + r) * ldb + k0 + ch * 8;
                cpa16(sB + r * 128 + ((ch ^ (r & 7)) << 4), src);
            }
        } else {
            constexpr int CPR = NTILE / 8;            /* 16B chunks per B row */
            #pragma unroll
            for (int i = 0; i < (64 * CPR) / 256; i++) {
                int li = tid + i * 256;
                int r = li / CPR, ch = li % CPR;
                const hf* src = Bh + (long long)(k0 + r) * ldb + colBase + ch * 8;
                cpa16(sB + r * (NTILE * 2) + ((ch ^ (r & 7)) << 4), src);
            }
        }
    };

    auto compute = [&](int s) {
        unsigned sA = smBase + s * STAGE;
        unsigned sB = sA + ABYTES;
        #pragma unroll
        for (int ks = 0; ks < 4; ks++) {
            unsigned ah[MF][4];
            #pragma unroll
            for (int mf = 0; mf < MF; mf++) {
                int ar = warpRow + mf * 16 + (lane & 15);
                int ac = ks * 2 + (lane >> 4);
                ldsm4(ah[mf][0], ah[mf][1], ah[mf][2], ah[mf][3],
                      sA + ar * 128 + ((ac ^ (ar & 7)) << 4));
            }
            #pragma unroll
            for (int np = 0; np < NF / 2; np++) {
                unsigned bh[2][2];
                if (!TB) {
                    int bk = ks * 16 + (lane & 15);
                    int nc = (warpCol + np * 16 + ((lane >> 4) << 3)) >> 3;
                    ldsm4t(bh[0][0], bh[0][1], bh[1][0], bh[1][1],
                           sB + bk * (NTILE * 2) + ((nc ^ (bk & 7)) << 4));
                } else {
                    int br = warpCol + np * 16 + ((lane >> 4) << 3) + (lane & 7);
                    int kc = ks * 2 + ((lane >> 3) & 1);
                    ldsm4(bh[0][0], bh[0][1], bh[1][0], bh[1][1],
                          sB + br * 128 + ((kc ^ (br & 7)) << 4));
                }
                #pragma unroll
                for (int mf = 0; mf < MF; mf++)
                    #pragma unroll
                    for (int j = 0; j < 2; j++) mma16816(acc[mf][2*np+j], ah[mf], bh[j]);
            }
        }
    };

    int nk = K / KT;
    issue(0, 0); CP_COMMIT();
    if (nk > 1) issue(1, KT);
    CP_COMMIT();
    for (int i = 0; i < nk; i++) {
        CP_WAIT1();
        __syncthreads();
        if (i + 2 < nk) issue((i + 2) % 3, (i + 2) * KT);
        CP_COMMIT();
        compute(i % 3);
    }

    #pragma unroll
    for (int mf = 0; mf < MF; mf++) {
        #pragma unroll
        for (int nf = 0; nf < NF; nf++) {
            int row = rowBase + warpRow + mf * 16 + (lane >> 2);
            int col = colBase + warpCol + nf * 8 + (lane & 3) * 2;
            float bx = 0.f, by = 0.f;
            if (bias) { float2 bb = *(const float2*)(bias + col); bx = bb.x; by = bb.y; }
            float v0 = acc[mf][nf][0] * alpha + bx;
            float v1 = acc[mf][nf][1] * alpha + by;
            float v2 = acc[mf][nf][2] * alpha + bx;
            float v3 = acc[mf][nf][3] * alpha + by;
            if (GELU) { v0 = gelu_f(v0); v1 = gelu_f(v1); v2 = gelu_f(v2); v3 = gelu_f(v3); }
            long long o0 = coff + (long long)row * ldc + col;
            long long o1 = coff + (long long)(row + 8) * ldc + col;
            if (OUTM == 0) {
                *(float2*)(C + o0) = make_float2(v0, v1);
                *(float2*)(C + o1) = make_float2(v2, v3);
            } else {
                *(hf2*)(Chi + o0) = __floats2half2_rn(v0, v1);
                *(hf2*)(Chi + o1) = __floats2half2_rn(v2, v3);
            }
        }
    }
}

/* ---------------- fused flash MHA (QK^T + softmax + PV), single fp16 ------
   Smem request padded to 132096 to pin 1 CTA/SM (R12-verified).            */
__global__ void __launch_bounds__(256, 1) flash_mha(
    const hf* __restrict__ QKVhi, hf* __restrict__ Ohi)
{
    extern __shared__ char dsm[];
    unsigned smRaw = (unsigned)__cvta_generic_to_shared(dsm);
    unsigned smQ  = (smRaw + 1023u) & ~1023u;    /* 16K */
    unsigned smKV = smQ + 16384;                 /* 3 stages x [KH 16K | VH 16K] */

    int bh = blockIdx.y;
    int b = bh >> 4, h = bh & 15;
    long long rowBase = (long long)b * NTOK;
    int qRow0 = blockIdx.x * 128;
    const int ld = 3 * DIMC;
    int qcol = h * 64, kcol = DIMC + h * 64, vcol = 2 * DIMC + h * 64;

    int tid = threadIdx.x, lane = tid & 31, w = tid >> 5;

    #pragma unroll
    for (int i = 0; i < 4; i++) {
        int li = tid + i * 256, r = li >> 3, ch = li & 7;
        unsigned sw = r * 128 + ((ch ^ (r & 7)) << 4);
        cpa16(smQ + sw, QKVhi + (rowBase + qRow0 + r) * ld + qcol + ch * 8);
    }
    CP_COMMIT();

    auto issueKV = [&](int s, int kt0) {
        unsigned base = smKV + s * 32768;
        #pragma unroll
        for (int i = 0; i < 4; i++) {
            int li = tid + i * 256, r = li >> 3, ch = li & 7;
            unsigned sw = r * 128 + ((ch ^ (r & 7)) << 4);
            long long g = (rowBase + kt0 + r) * ld;
            cpa16(base + sw,         QKVhi + g + kcol + ch * 8);
            cpa16(base + 16384 + sw, QKVhi + g + vcol + ch * 8);
        }
    };

    issueKV(0, 0);   CP_COMMIT();
    issueKV(1, 128); CP_COMMIT();

    CP_WAIT2();
    __syncthreads();

    unsigned qh[4][4];
    {
        int ar = w * 16 + (lane & 15);
        hf2 s2 = __floats2half2_rn(0.125f, 0.125f);
        #pragma unroll
        for (int c = 0; c < 4; c++) {
            int ac = c * 2 + (lane >> 4);
            ldsm4(qh[c][0], qh[c][1], qh[c][2], qh[c][3],
                  smQ + ar * 128 + ((ac ^ (ar & 7)) << 4));
            #pragma unroll
            for (int r = 0; r < 4; r++) {
                hf2 t = *(hf2*)&qh[c][r]; t = __hmul2(t, s2); qh[c][r] = *(unsigned*)&t;
            }
        }
    }

    float o[8][4] = {};
    float l0 = 0.f, l1 = 0.f;

    for (int kt = 0; kt < 16; kt++) {
        CP_WAIT1();
        __syncthreads();
        if (kt + 2 < 16) issueKV((kt + 2) % 3, (kt + 2) * 128);
        CP_COMMIT();

        unsigned base = smKV + (kt % 3) * 32768;

        float sacc[16][4] = {};
        #pragma unroll
        for (int c = 0; c < 4; c++) {
            #pragma unroll
            for (int np = 0; np < 8; np++) {
                unsigned kh2[2][2];
                int br = np * 16 + ((lane >> 4) << 3) + (lane & 7);
                int kc = c * 2 + ((lane >> 3) & 1);
                ldsm4(kh2[0][0], kh2[0][1], kh2[1][0], kh2[1][1],
                      base + br * 128 + ((kc ^ (br & 7)) << 4));
                #pragma unroll
                for (int j = 0; j < 2; j++) mma16816(sacc[2*np+j], qh[c], kh2[j]);
            }
        }

        unsigned ph[8][4];
        #pragma unroll
        for (int f = 0; f < 16; f++) {
            float p0 = __expf(sacc[f][0]);
            float p1 = __expf(sacc[f][1]);
            float p2 = __expf(sacc[f][2]);
            float p3 = __expf(sacc[f][3]);
            l0 += p0 + p1;
            l1 += p2 + p3;
            int j = f >> 1, hfi = f & 1;
            hf2 a = __floats2half2_rn(p0, p1);
            hf2 c = __floats2half2_rn(p2, p3);
            ph[j][hfi*2+0] = *(unsigned*)&a;
            ph[j][hfi*2+1] = *(unsigned*)&c;
        }

        unsigned vb = base + 16384;
        #pragma unroll
        for (int j = 0; j < 8; j++) {
            #pragma unroll
            for (int np2 = 0; np2 < 4; np2++) {
                unsigned vh[2][2];
                int bk = j * 16 + (lane & 15);
                int nc = (np2 * 16 + ((lane >> 4) << 3)) >> 3;
                ldsm4t(vh[0][0], vh[0][1], vh[1][0], vh[1][1],
                       vb + bk * 128 + ((nc ^ (bk & 7)) << 4));
                #pragma unroll
                for (int t = 0; t < 2; t++) mma16816(o[2*np2+t], ph[j], vh[t]);
            }
        }
    }

    l0 += __shfl_xor_sync(0xffffffffu, l0, 1);
    l0 += __shfl_xor_sync(0xffffffffu, l0, 2);
    l1 += __shfl_xor_sync(0xffffffffu, l1, 1);
    l1 += __shfl_xor_sync(0xffffffffu, l1, 2);
    float i0 = 1.0f / l0, i1 = 1.0f / l1;

    long long or0 = (rowBase + qRow0 + w * 16 + (lane >> 2)) * DIMC + h * 64;
    #pragma unroll
    for (int nf = 0; nf < 8; nf++) {
        int col = nf * 8 + (lane & 3) * 2;
        *(hf2*)(Ohi + or0 + col)            = __floats2half2_rn(o[nf][0] * i0, o[nf][1] * i0);
        *(hf2*)(Ohi + or0 + 8 * DIMC + col) = __floats2half2_rn(o[nf][2] * i1, o[nf][3] * i1);
    }
}

/* ---------------- merged weight convert: all 8 weights, one launch -------- */
__global__ void __launch_bounds__(256) conv_all(
    const float* __restrict__ qkv_w, const float* __restrict__ proj_w,
    const float* __restrict__ kq_w,  const float* __restrict__ kk_w,
    const float* __restrict__ kv_w,  const float* __restrict__ ko_w,
    const float* __restrict__ fc1_w, const float* __restrict__ fc2_w,
    hf* __restrict__ whi)
{
    int blk = blockIdx.x, tid = threadIdx.x;
    const float* src;
    hf* dst;
    if (blk < 3072)      { src = qkv_w  + (long long)blk * 1024; dst = whi + W_QKV  + (long long)blk * 1024; }
    else if (blk < 4096) { src = proj_w + (long long)(blk - 3072) * 1024; dst = whi + W_PROJ + (long long)(blk - 3072) * 1024; }
    else if (blk < 5120) { int r = blk - 4096; src = kq_w + (long long)r * 1024; dst = whi + W_KQKV + (long long)r * 3072; }
    else if (blk < 6144) { int r = blk - 5120; src = kk_w + (long long)r * 1024; dst = whi + W_KQKV + (long long)r * 3072 + 1024; }
    else if (blk < 7168) { int r = blk - 6144; src = kv_w + (long long)r * 1024; dst = whi + W_KQKV + (long long)r * 3072 + 2048; }
    else if (blk < 8192) { src = ko_w  + (long long)(blk - 7168) * 1024; dst = whi + W_KO  + (long long)(blk - 7168) * 1024; }
    else if (blk < 12288){ src = fc1_w + (long long)(blk - 8192) * 1024; dst = whi + W_FC1 + (long long)(blk - 8192) * 1024; }
    else                 { src = fc2_w + (long long)(blk - 12288) * 1024; dst = whi + W_FC2 + (long long)(blk - 12288) * 1024; }
    float4 v = *(const float4*)(src + tid * 4);
    *(hf2*)(dst + tid * 4)     = __floats2half2_rn(v.x, v.y);
    *(hf2*)(dst + tid * 4 + 2) = __floats2half2_rn(v.z, v.w);
}

__global__ void __launch_bounds__(256) concat_bias(
    const float* __restrict__ a, const float* __restrict__ b,
    const float* __restrict__ c, float* __restrict__ o)
{
    int i = blockIdx.x * 256 + threadIdx.x;
    o[i] = (i < 1024) ? a[i] : ((i < 2048) ? b[i - 1024] : c[i - 2048]);
}

/* ---------------- theta + softmax -> fp16 (hi only) ----------------------- */
__global__ void __launch_bounds__(256) theta_softmax2048_hf(
    const float* __restrict__ S, hf* __restrict__ Phi)
{
    __shared__ float red[8];
    const float* row = S + (long long)blockIdx.x * 2048;
    long long ob = (long long)blockIdx.x * 2048;
    int tid = threadIdx.x;
    float4 v0 = ((const float4*)row)[tid];
    float4 v1 = ((const float4*)row)[tid + 256];
    v0.x = theta_fn(v0.x); v0.y = theta_fn(v0.y); v0.z = theta_fn(v0.z); v0.w = theta_fn(v0.w);
    v1.x = theta_fn(v1.x); v1.y = theta_fn(v1.y); v1.z = theta_fn(v1.z); v1.w = theta_fn(v1.w);
    float m = fmaxf(fmaxf(fmaxf(v0.x, v0.y), fmaxf(v0.z, v0.w)),
                    fmaxf(fmaxf(v1.x, v1.y), fmaxf(v1.z, v1.w)));
    #pragma unroll
    for (int o = 16; o; o >>= 1) m = fmaxf(m, __shfl_xor_sync(0xffffffffu, m, o));
    if ((tid & 31) == 0) red[tid >> 5] = m;
    __syncthreads();
    m = fmaxf(fmaxf(fmaxf(red[0], red[1]), fmaxf(red[2], red[3])),
              fmaxf(fmaxf(red[4], red[5]), fmaxf(red[6], red[7])));
    v0.x = __expf(v0.x - m); v0.y = __expf(v0.y - m); v0.z = __expf(v0.z - m); v0.w = __expf(v0.w - m);
    v1.x = __expf(v1.x - m); v1.y = __expf(v1.y - m); v1.z = __expf(v1.z - m); v1.w = __expf(v1.w - m);
    float s = v0.x + v0.y + v0.z + v0.w + v1.x + v1.y + v1.z + v1.w;
    #pragma unroll
    for (int o = 16; o; o >>= 1) s += __shfl_xor_sync(0xffffffffu, s, o);
    __syncthreads();
    if ((tid & 31) == 0) red[tid >> 5] = s;
    __syncthreads();
    s = red[0] + red[1] + red[2] + red[3] + red[4] + red[5] + red[6] + red[7];
    float r = 1.0f / s;
    v0.x *= r; v0.y *= r; v0.z *= r; v0.w *= r;
    v1.x *= r; v1.y *= r; v1.z *= r; v1.w *= r;
    *(hf2*)(Phi + ob + tid*4)            = __floats2half2_rn(v0.x, v0.y);
    *(hf2*)(Phi + ob + tid*4 + 2)        = __floats2half2_rn(v0.z, v0.w);
    *(hf2*)(Phi + ob + 1024 + tid*4)     = __floats2half2_rn(v1.x, v1.y);
    *(hf2*)(Phi + ob + 1024 + tid*4 + 2) = __floats2half2_rn(v1.z, v1.w);
}

/* ---------------- LayerNorm over 1024 -> fp16 ----------------------------- */
__global__ void __launch_bounds__(256) layernorm1024_hf(
    const float* __restrict__ X, const float* __restrict__ g,
    const float* __restrict__ bta, hf* __restrict__ Yhi)
{
    __shared__ float rs[8], rq[8];
    long long base = (long long)blockIdx.x * 1024;
    int tid = threadIdx.x;
    float4 v = *(const float4*)(X + base + tid * 4);
    float s = v.x + v.y + v.z + v.w;
    float q = v.x*v.x + v.y*v.y + v.z*v.z + v.w*v.w;
    #pragma unroll
    for (int o = 16; o; o >>= 1) {
        s += __shfl_xor_sync(0xffffffffu, s, o);
        q += __shfl_xor_sync(0xffffffffu, q, o);
    }
    if ((tid & 31) == 0) { rs[tid >> 5] = s; rq[tid >> 5] = q; }
    __syncthreads();
    s = rs[0] + rs[1] + rs[2] + rs[3] + rs[4] + rs[5] + rs[6] + rs[7];
    q = rq[0] + rq[1] + rq[2] + rq[3] + rq[4] + rq[5] + rq[6] + rq[7];
    float mu  = s * (1.0f / 1024.0f);
    float var = q * (1.0f / 1024.0f) - mu * mu;
    float inv = rsqrtf(var + 1e-5f);
    float4 gg = *(const float4*)(g + tid * 4);
    float4 bb = *(const float4*)(bta + tid * 4);
    float o0 = (v.x - mu) * inv * gg.x + bb.x;
    float o1 = (v.y - mu) * inv * gg.y + bb.y;
    float o2 = (v.z - mu) * inv * gg.z + bb.z;
    float o3 = (v.w - mu) * inv * gg.w + bb.w;
    *(hf2*)(Yhi + base + tid*4)     = __floats2half2_rn(o0, o1);
    *(hf2*)(Yhi + base + tid*4 + 2) = __floats2half2_rn(o2, o3);
}

/* ---------------- residual adds ------------------------------------------- */
__global__ void __launch_bounds__(256) add_hf(
    float* __restrict__ out, const float* __restrict__ a, const float* __restrict__ b,
    hf* __restrict__ hi)
{
    long long i = ((long long)blockIdx.x * 256 + threadIdx.x) * 4;
    float4 av = *(const float4*)(a + i);
    float4 bv = *(const float4*)(b + i);
    av.x += bv.x; av.y += bv.y; av.z += bv.z; av.w += bv.w;
    *(float4*)(out + i) = av;
    *(hf2*)(hi + i)     = __floats2half2_rn(av.x, av.y);
    *(hf2*)(hi + i + 2) = __floats2half2_rn(av.z, av.w);
}
__global__ void __launch_bounds__(256) add_plain(
    float* __restrict__ out, const float* __restrict__ b)
{
    long long i = ((long long)blockIdx.x * 256 + threadIdx.x) * 4;
    float4 av = *(const float4*)(out + i);
    float4 bv = *(const float4*)(b + i);
    av.x += bv.x; av.y += bv.y; av.z += bv.z; av.w += bv.w;
    *(float4*)(out + i) = av;
}

/* ---------------- host-side dispatch -------------------------------------- */
#define SMEM_G     99328    /* 3*(16384+16384) + 1024 ; 2 CTAs/SM */
#define SMEM_FLASH 132096   /* needs 115712; padded to pin 1 CTA/SM */

extern "C" void kernel_launch(void* const* d_in, const int* in_sizes, int n_in,
                              void* d_out, int out_size)
{
    const float* x     = (const float*)d_in[0];
    const float* ln1_g = (const float*)d_in[1];
    const float* ln1_b = (const float*)d_in[2];
    const float* qkv_w = (const float*)d_in[3];
    const float* qkv_b = (const float*)d_in[4];
    const float* proj_w= (const float*)d_in[5];
    const float* proj_b= (const float*)d_in[6];
    const float* kq_w  = (const float*)d_in[7];
    const float* kq_b  = (const float*)d_in[8];
    const float* kk_w  = (const float*)d_in[9];
    const float* kk_b  = (const float*)d_in[10];
    const float* kv_w  = (const float*)d_in[11];
    const float* kv_b  = (const float*)d_in[12];
    const float* ko_w  = (const float*)d_in[13];
    const float* ko_b  = (const float*)d_in[14];
    const float* ln2_g = (const float*)d_in[15];
    const float* ln2_b = (const float*)d_in[16];
    const float* fc1_w = (const float*)d_in[17];
    const float* fc1_b = (const float*)d_in[18];
    const float* fc2_w = (const float*)d_in[19];
    const float* fc2_b = (const float*)d_in[20];
    float* out = (float*)d_out;

    float *sc, *bufA, *bias3;
    hf *whi, *lnhi, *qkvhi, *schi, *aohi, *reshi, *ffhi;
    cudaGetSymbolAddress((void**)&sc,    g_sc);
    cudaGetSymbolAddress((void**)&bufA,  g_bufA);
    cudaGetSymbolAddress((void**)&bias3, g_bias3);
    cudaGetSymbolAddress((void**)&whi,   g_whi);
    cudaGetSymbolAddress((void**)&lnhi,  g_lnhi);
    cudaGetSymbolAddress((void**)&qkvhi, g_qkvhi);
    cudaGetSymbolAddress((void**)&schi,  g_schi);
    cudaGetSymbolAddress((void**)&aohi,  g_aohi);
    cudaGetSymbolAddress((void**)&reshi, g_reshi);
    cudaGetSymbolAddress((void**)&ffhi,  g_ffhi);

    cudaFuncSetAttribute(bgemm<128, false, false, 1>, cudaFuncAttributeMaxDynamicSharedMemorySize, SMEM_G);
    cudaFuncSetAttribute(bgemm<128, false, false, 0>, cudaFuncAttributeMaxDynamicSharedMemorySize, SMEM_G);
    cudaFuncSetAttribute(bgemm<128, false, true,  1>, cudaFuncAttributeMaxDynamicSharedMemorySize, SMEM_G);
    cudaFuncSetAttribute(bgemm<128, true,  false, 0>, cudaFuncAttributeMaxDynamicSharedMemorySize, SMEM_G);
    cudaFuncSetAttribute(flash_mha, cudaFuncAttributeMaxDynamicSharedMemorySize, SMEM_FLASH);

    const long long NN = (long long)NTOK * NTOK;
    const long long TC = (long long)NTOK * DIMC;
    const int nElemBlks = (TTOK * DIMC) / (4 * 256);
    dim3 tb(256);

    /* weight conversion: one launch for all 8 matrices */
    conv_all<<<16384, tb>>>(qkv_w, proj_w, kq_w, kk_w, kv_w, ko_w, fc1_w, fc2_w, whi);
    concat_bias<<<12, tb>>>(kq_b, kk_b, kv_b, bias3);
    layernorm1024_hf<<<TTOK, tb>>>(x, ln1_g, ln1_b, lnhi);

    /* qkv = ln1 @ qkv_w + b */
    bgemm<128, false, false, 1><<<dim3(24, 32, 1), tb, SMEM_G>>>(
        lnhi, whi + W_QKV, nullptr, qkvhi, qkv_b,
        1024, 1024, 3072, 3072, 1, 0,0, 0,0, 0,0, 1.0f);

    /* fused MHA attention -> aohi */
    flash_mha<<<dim3(16, 32), tb, SMEM_FLASH>>>(qkvhi, aohi);

    bgemm<128, false, false, 0><<<dim3(8, 32, 1), tb, SMEM_G>>>(
        aohi, whi + W_PROJ, bufA, nullptr, proj_b,
        1024, 1024, 1024, 1024, 1, 0,0, 0,0, 0,0, 1.0f);
    add_hf<<<nElemBlks, tb>>>(out, x, bufA, reshi);

    /* ---- sublayer 2: kernel attention ---- */
    /* merged q|k|v = res @ [kq|kk|kv] + [biases] -> qkvhi [T, 3072] */
    bgemm<128, false, false, 1><<<dim3(24, 32, 1), tb, SMEM_G>>>(
        reshi, whi + W_KQKV, nullptr, qkvhi, bias3,
        1024, 1024, 3072, 3072, 1, 0,0, 0,0, 0,0, 1.0f);

    hf* bqhi = qkvhi;
    hf* bkhi = qkvhi + DIMC;
    hf* bvhi = qkvhi + 2 * DIMC;

    /* qk = q @ k^T per batch (single-A TB, k-tile 64, ld 3072) */
    bgemm<128, true, false, 0><<<dim3(16, 16, BATCHN), tb, SMEM_G>>>(
        bqhi, bkhi, sc, nullptr, nullptr,
        1024, 3072, 3072, NTOK, 1,
        (long long)NTOK*3*DIMC, 0, (long long)NTOK*3*DIMC, 0, NN, 0, 1.0f);

    theta_softmax2048_hf<<<BATCHN*NTOK, tb>>>(sc, schi);

    /* av = attn @ v per batch (single-A NN, ldb 3072) */
    bgemm<128, false, false, 1><<<dim3(8, 16, BATCHN), tb, SMEM_G>>>(
        schi, bvhi, nullptr, aohi, nullptr,
        NTOK, NTOK, 3*DIMC, DIMC, 1,
        NN, 0, (long long)NTOK*3*DIMC, 0, TC, 0, 1.0f);

    bgemm<128, false, false, 0><<<dim3(8, 32, 1), tb, SMEM_G>>>(
        aohi, whi + W_KO, bufA, nullptr, ko_b,
        1024, 1024, 1024, 1024, 1, 0,0, 0,0, 0,0, 1.0f);
    add_plain<<<nElemBlks, tb>>>(out, bufA);

    /* ---- sublayer 3: FFN ---- */
    layernorm1024_hf<<<TTOK, tb>>>(out, ln2_g, ln2_b, lnhi);
    bgemm<128, false, true, 1><<<dim3(32, 32, 1), tb, SMEM_G>>>(
        lnhi, whi + W_FC1, nullptr, ffhi, fc1_b,
        1024, 1024, 4096, 4096, 1, 0,0, 0,0, 0,0, 1.0f);
    bgemm<128, false, false, 0><<<dim3(8, 32, 1), tb, SMEM_G>>>(
        ffhi, whi + W_FC2, bufA, nullptr, fc2_b,
        4096, 4096, 1024, 1024, 1, 0,0, 0,0, 0,0, 1.0f);
    add_plain<<<nElemBlks, tb>>>(out, bufA);
}

// round 17
// speedup vs baseline: 1.6053x; 1.0078x over previous
#include <cuda_runtime.h>
#include <cuda_fp16.h>
#include <math.h>

#define DIMC 1024
#define NTOK 2048
#define BATCHN 2
#define TTOK (BATCHN*NTOK)
#define NHEADS 16
#define HDIM 64
#define DFF 4096

typedef __half hf;
typedef __half2 hf2;

/* ---------------- scratch (device globals; no allocations allowed) -------- */
__device__ float g_sc  [(size_t)BATCHN*NTOK*NTOK];
__device__ float g_bufA[(size_t)TTOK*DIMC];
__device__ float g_bias3[3072];
__device__ hf g_whi[16777216];
__device__ hf g_lnhi [(size_t)TTOK*DIMC];
__device__ hf g_qkvhi[(size_t)TTOK*3*DIMC];
__device__ hf g_schi [(size_t)BATCHN*NTOK*NTOK];
__device__ hf g_aohi [(size_t)TTOK*DIMC];
__device__ hf g_reshi[(size_t)TTOK*DIMC];
__device__ hf g_ffhi [(size_t)TTOK*DFF];

#define W_QKV  0LL
#define W_PROJ 3145728LL
#define W_KQKV 4194304LL
#define W_KO   7340032LL
#define W_FC1  8388608LL
#define W_FC2  12582912LL

/* ---------------- helpers ------------------------------------------------- */
__device__ __forceinline__ float gelu_f(float x) {
    return 0.5f * x * (1.0f + erff(x * 0.7071067811865476f));
}
__device__ __forceinline__ float theta_fn(float x) {
    float sg = 1.0f / (1.0f + __expf(-x));
    float rl = fmaxf(x, 0.0f);
    return 0.5f + 0.2f * sg + 0.15f * tanhf(x) + 0.1f * rl;
}
__device__ __forceinline__ void ldsm4(unsigned& r0, unsigned& r1, unsigned& r2, unsigned& r3, unsigned a) {
    asm volatile("ldmatrix.sync.aligned.m8n8.x4.shared.b16 {%0,%1,%2,%3}, [%4];"
                 : "=r"(r0), "=r"(r1), "=r"(r2), "=r"(r3) : "r"(a));
}
__device__ __forceinline__ void ldsm4t(unsigned& r0, unsigned& r1, unsigned& r2, unsigned& r3, unsigned a) {
    asm volatile("ldmatrix.sync.aligned.m8n8.x4.trans.shared.b16 {%0,%1,%2,%3}, [%4];"
                 : "=r"(r0), "=r"(r1), "=r"(r2), "=r"(r3) : "r"(a));
}
__device__ __forceinline__ void mma16816(float* d, const unsigned* a, const unsigned* b) {
    asm volatile(
        "mma.sync.aligned.m16n8k16.row.col.f32.f16.f16.f32 "
        "{%0,%1,%2,%3}, {%4,%5,%6,%7}, {%8,%9}, {%0,%1,%2,%3};"
        : "+f"(d[0]), "+f"(d[1]), "+f"(d[2]), "+f"(d[3])
        : "r"(a[0]), "r"(a[1]), "r"(a[2]), "r"(a[3]), "r"(b[0]), "r"(b[1]));
}
__device__ __forceinline__ void cpa16(unsigned dst, const void* src) {
    asm volatile("cp.async.cg.shared.global [%0], [%1], 16;" :: "r"(dst), "l"(src));
}
#define CP_COMMIT() asm volatile("cp.async.commit_group;")
#define CP_WAIT1()  asm volatile("cp.async.wait_group 1;")
#define CP_WAIT2()  asm volatile("cp.async.wait_group 2;")

/* ---------------- fp16 tensor-core GEMM (R15, unchanged) ------------------ */
template<int NTILE, bool TB, bool GELU, int OUTM>
__global__ void __launch_bounds__(256, 2) bgemm(
    const hf* __restrict__ Ahi, const hf* __restrict__ Bhi,
    float* __restrict__ C, hf* __restrict__ Chi,
    const float* __restrict__ bias,
    int K, int lda, int ldb, int ldc, int zdiv,
    long long sA1, long long sA2, long long sB1, long long sB2,
    long long sC1, long long sC2, float alpha)
{
    extern __shared__ char dsm[];
    constexpr int KT     = 64;
    constexpr int ABYTES = 16384;
    constexpr int BBYTES = NTILE * 128;
    constexpr int STAGE  = ABYTES + BBYTES;

    unsigned smRaw  = (unsigned)__cvta_generic_to_shared(dsm);
    unsigned smBase = (smRaw + 1023u) & ~1023u;

    int z = blockIdx.z, z1 = z / zdiv, z2 = z % zdiv;
    const hf* Ah = Ahi + z1 * sA1 + z2 * sA2;
    const hf* Bh = Bhi + z1 * sB1 + z2 * sB2;
    long long coff = z1 * sC1 + z2 * sC2;

    int rowBase = blockIdx.y * 128;
    int colBase = blockIdx.x * NTILE;
    int tid = threadIdx.x, lane = tid & 31, w = tid >> 5;

    constexpr int MF = 4;
    constexpr int NF = NTILE / 32;
    int warpRow = (w & 1) * 64;
    int warpCol = (w >> 1) * (NTILE / 4);

    float acc[MF][NF][4] = {};

    auto issue = [&](int s, int k0) {
        unsigned sA = smBase + s * STAGE;
        unsigned sB = sA + ABYTES;
        #pragma unroll
        for (int i = 0; i < 4; i++) {
            int li = tid + i * 256, r = li >> 3, ch = li & 7;
            const hf* src = Ah + (long long)(rowBase + r) * lda + k0 + ch * 8;
            cpa16(sA + r * 128 + ((ch ^ (r & 7)) << 4), src);
        }
        if (TB) {
            #pragma unroll
            for (int i = 0; i < NTILE / 32; i++) {
                int li = tid + i * 256, r = li >> 3, ch = li & 7;
                const hf* src = Bh + (long long)(colBase + r) * ldb + k0 + ch * 8;
                cpa16(sB + r * 128 + ((ch ^ (r & 7)) << 4), src);
            }
        } else {
            constexpr int CPR = NTILE / 8;
            #pragma unroll
            for (int i = 0; i < (64 * CPR) / 256; i++) {
                int li = tid + i * 256;
                int r = li / CPR, ch = li % CPR;
                const hf* src = Bh + (long long)(k0 + r) * ldb + colBase + ch * 8;
                cpa16(sB + r * (NTILE * 2) + ((ch ^ (r & 7)) << 4), src);
            }
        }
    };

    auto compute = [&](int s) {
        unsigned sA = smBase + s * STAGE;
        unsigned sB = sA + ABYTES;
        #pragma unroll
        for (int ks = 0; ks < 4; ks++) {
            unsigned ah[MF][4];
            #pragma unroll
            for (int mf = 0; mf < MF; mf++) {
                int ar = warpRow + mf * 16 + (lane & 15);
                int ac = ks * 2 + (lane >> 4);
                ldsm4(ah[mf][0], ah[mf][1], ah[mf][2], ah[mf][3],
                      sA + ar * 128 + ((ac ^ (ar & 7)) << 4));
            }
            #pragma unroll
            for (int np = 0; np < NF / 2; np++) {
                unsigned bh[2][2];
                if (!TB) {
                    int bk = ks * 16 + (lane & 15);
                    int nc = (warpCol + np * 16 + ((lane >> 4) << 3)) >> 3;
                    ldsm4t(bh[0][0], bh[0][1], bh[1][0], bh[1][1],
                           sB + bk * (NTILE * 2) + ((nc ^ (bk & 7)) << 4));
                } else {
                    int br = warpCol + np * 16 + ((lane >> 4) << 3) + (lane & 7);
                    int kc = ks * 2 + ((lane >> 3) & 1);
                    ldsm4(bh[0][0], bh[0][1], bh[1][0], bh[1][1],
                          sB + br * 128 + ((kc ^ (br & 7)) << 4));
                }
                #pragma unroll
                for (int mf = 0; mf < MF; mf++)
                    #pragma unroll
                    for (int j = 0; j < 2; j++) mma16816(acc[mf][2*np+j], ah[mf], bh[j]);
            }
        }
    };

    int nk = K / KT;
    issue(0, 0); CP_COMMIT();
    if (nk > 1) issue(1, KT);
    CP_COMMIT();
    for (int i = 0; i < nk; i++) {
        CP_WAIT1();
        __syncthreads();
        if (i + 2 < nk) issue((i + 2) % 3, (i + 2) * KT);
        CP_COMMIT();
        compute(i % 3);
    }

    #pragma unroll
    for (int mf = 0; mf < MF; mf++) {
        #pragma unroll
        for (int nf = 0; nf < NF; nf++) {
            int row = rowBase + warpRow + mf * 16 + (lane >> 2);
            int col = colBase + warpCol + nf * 8 + (lane & 3) * 2;
            float bx = 0.f, by = 0.f;
            if (bias) { float2 bb = *(const float2*)(bias + col); bx = bb.x; by = bb.y; }
            float v0 = acc[mf][nf][0] * alpha + bx;
            float v1 = acc[mf][nf][1] * alpha + by;
            float v2 = acc[mf][nf][2] * alpha + bx;
            float v3 = acc[mf][nf][3] * alpha + by;
            if (GELU) { v0 = gelu_f(v0); v1 = gelu_f(v1); v2 = gelu_f(v2); v3 = gelu_f(v3); }
            long long o0 = coff + (long long)row * ldc + col;
            long long o1 = coff + (long long)(row + 8) * ldc + col;
            if (OUTM == 0) {
                *(float2*)(C + o0) = make_float2(v0, v1);
                *(float2*)(C + o1) = make_float2(v2, v3);
            } else {
                *(hf2*)(Chi + o0) = __floats2half2_rn(v0, v1);
                *(hf2*)(Chi + o1) = __floats2half2_rn(v2, v3);
            }
        }
    }
}

/* ---------------- fused flash MHA, q-tile 64, 2 CTAs/SM --------------------
   8 warps = 4 row-groups x 2 column-halves. Each warp: 16 q-rows x 64 of
   128 S-cols per k-tile -> partial O and row-sums; smem reduce at end.     */
__global__ void __launch_bounds__(256, 2) flash_mha(
    const hf* __restrict__ QKVhi, hf* __restrict__ Ohi)
{
    extern __shared__ char dsm[];
    unsigned smRaw = (unsigned)__cvta_generic_to_shared(dsm);
    unsigned smQ  = (smRaw + 1023u) & ~1023u;    /* 8K (64 rows) */
    unsigned smKV = smQ + 8192;                  /* 3 stages x [KH 16K | VH 16K] */

    int bh = blockIdx.y;
    int b = bh >> 4, h = bh & 15;
    long long rowBase = (long long)b * NTOK;
    int qRow0 = blockIdx.x * 64;
    const int ld = 3 * DIMC;
    int qcol = h * 64, kcol = DIMC + h * 64, vcol = 2 * DIMC + h * 64;

    int tid = threadIdx.x, lane = tid & 31, w = tid >> 5;
    int wr = w & 3;              /* row group: rows wr*16.. */
    int chalf = w >> 2;          /* column half: S-cols chalf*64.. */

    #pragma unroll
    for (int i = 0; i < 2; i++) {
        int li = tid + i * 256, r = li >> 3, ch = li & 7;
        unsigned sw = r * 128 + ((ch ^ (r & 7)) << 4);
        cpa16(smQ + sw, QKVhi + (rowBase + qRow0 + r) * ld + qcol + ch * 8);
    }
    CP_COMMIT();

    auto issueKV = [&](int s, int kt0) {
        unsigned base = smKV + s * 32768;
        #pragma unroll
        for (int i = 0; i < 4; i++) {
            int li = tid + i * 256, r = li >> 3, ch = li & 7;
            unsigned sw = r * 128 + ((ch ^ (r & 7)) << 4);
            long long g = (rowBase + kt0 + r) * ld;
            cpa16(base + sw,         QKVhi + g + kcol + ch * 8);
            cpa16(base + 16384 + sw, QKVhi + g + vcol + ch * 8);
        }
    };

    issueKV(0, 0);   CP_COMMIT();
    issueKV(1, 128); CP_COMMIT();

    CP_WAIT2();
    __syncthreads();

    unsigned qh[4][4];
    {
        int ar = wr * 16 + (lane & 15);
        hf2 s2 = __floats2half2_rn(0.125f, 0.125f);
        #pragma unroll
        for (int c = 0; c < 4; c++) {
            int ac = c * 2 + (lane >> 4);
            ldsm4(qh[c][0], qh[c][1], qh[c][2], qh[c][3],
                  smQ + ar * 128 + ((ac ^ (ar & 7)) << 4));
            #pragma unroll
            for (int r = 0; r < 4; r++) {
                hf2 t = *(hf2*)&qh[c][r]; t = __hmul2(t, s2); qh[c][r] = *(unsigned*)&t;
            }
        }
    }

    float o[8][4] = {};
    float l0 = 0.f, l1 = 0.f;

    for (int kt = 0; kt < 16; kt++) {
        CP_WAIT1();
        __syncthreads();
        if (kt + 2 < 16) issueKV((kt + 2) % 3, (kt + 2) * 128);
        CP_COMMIT();

        unsigned base = smKV + (kt % 3) * 32768;

        /* S = Q @ K^T : 16 rows x 64 cols (this warp's column half) */
        float sacc[8][4] = {};
        #pragma unroll
        for (int c = 0; c < 4; c++) {
            #pragma unroll
            for (int np = 0; np < 4; np++) {
                unsigned kh2[2][2];
                int br = chalf * 64 + np * 16 + ((lane >> 4) << 3) + (lane & 7);
                int kc = c * 2 + ((lane >> 3) & 1);
                ldsm4(kh2[0][0], kh2[0][1], kh2[1][0], kh2[1][1],
                      base + br * 128 + ((kc ^ (br & 7)) << 4));
                #pragma unroll
                for (int j = 0; j < 2; j++) mma16816(sacc[2*np+j], qh[c], kh2[j]);
            }
        }

        /* P = exp(S), partial row sums, pack to fp16 A-fragments */
        unsigned ph[4][4];
        #pragma unroll
        for (int f = 0; f < 8; f++) {
            float p0 = __expf(sacc[f][0]);
            float p1 = __expf(sacc[f][1]);
            float p2 = __expf(sacc[f][2]);
            float p3 = __expf(sacc[f][3]);
            l0 += p0 + p1;
            l1 += p2 + p3;
            int j = f >> 1, hfi = f & 1;
            hf2 a = __floats2half2_rn(p0, p1);
            hf2 c = __floats2half2_rn(p2, p3);
            ph[j][hfi*2+0] = *(unsigned*)&a;
            ph[j][hfi*2+1] = *(unsigned*)&c;
        }

        /* O += P @ V over this warp's 64 s-cols */
        unsigned vb = base + 16384;
        #pragma unroll
        for (int j = 0; j < 4; j++) {
            #pragma unroll
            for (int np2 = 0; np2 < 4; np2++) {
                unsigned vh[2][2];
                int bk = chalf * 64 + j * 16 + (lane & 15);
                int nc = (np2 * 16 + ((lane >> 4) << 3)) >> 3;
                ldsm4t(vh[0][0], vh[0][1], vh[1][0], vh[1][1],
                       vb + bk * 128 + ((nc ^ (bk & 7)) << 4));
                #pragma unroll
                for (int t = 0; t < 2; t++) mma16816(o[2*np2+t], ph[j], vh[t]);
            }
        }
    }

    /* in-warp reduce partial l over the 4-lane quad */
    l0 += __shfl_xor_sync(0xffffffffu, l0, 1);
    l0 += __shfl_xor_sync(0xffffffffu, l0, 2);
    l1 += __shfl_xor_sync(0xffffffffu, l1, 1);
    l1 += __shfl_xor_sync(0xffffffffu, l1, 2);

    /* cross-column-half reduction via smem (reuse KV stage 1, now idle) */
    __syncthreads();
    float* po = (float*)(dsm + (smQ - smRaw) + 8192 + 32768);  /* 16 KB */
    float* pl = po + 4096;                                     /* 128 floats */
    if (chalf == 1) {
        float* ob = po + wr * 1024;
        #pragma unroll
        for (int nf = 0; nf < 8; nf++) {
            int col = nf * 8 + (lane & 3) * 2;
            int r0 = lane >> 2;
            ob[r0 * 64 + col]       = o[nf][0];
            ob[r0 * 64 + col + 1]   = o[nf][1];
            ob[(r0+8) * 64 + col]   = o[nf][2];
            ob[(r0+8) * 64 + col+1] = o[nf][3];
        }
        if ((lane & 3) == 0) {
            pl[wr * 16 + (lane >> 2)]     = l0;
            pl[wr * 16 + 8 + (lane >> 2)] = l1;
        }
    }
    __syncthreads();
    if (chalf == 0) {
        float* ob = po + wr * 1024;
        int r0 = lane >> 2;
        float lt0 = l0 + pl[wr * 16 + r0];
        float lt1 = l1 + pl[wr * 16 + 8 + r0];
        float i0 = 1.0f / lt0, i1 = 1.0f / lt1;
        long long or0 = (rowBase + qRow0 + wr * 16 + r0) * DIMC + h * 64;
        #pragma unroll
        for (int nf = 0; nf < 8; nf++) {
            int col = nf * 8 + (lane & 3) * 2;
            float v0 = (o[nf][0] + ob[r0 * 64 + col])       * i0;
            float v1 = (o[nf][1] + ob[r0 * 64 + col + 1])   * i0;
            float v2 = (o[nf][2] + ob[(r0+8) * 64 + col])   * i1;
            float v3 = (o[nf][3] + ob[(r0+8) * 64 + col+1]) * i1;
            *(hf2*)(Ohi + or0 + col)            = __floats2half2_rn(v0, v1);
            *(hf2*)(Ohi + or0 + 8 * DIMC + col) = __floats2half2_rn(v2, v3);
        }
    }
}

/* ---------------- merged weight convert ----------------------------------- */
__global__ void __launch_bounds__(256) conv_all(
    const float* __restrict__ qkv_w, const float* __restrict__ proj_w,
    const float* __restrict__ kq_w,  const float* __restrict__ kk_w,
    const float* __restrict__ kv_w,  const float* __restrict__ ko_w,
    const float* __restrict__ fc1_w, const float* __restrict__ fc2_w,
    hf* __restrict__ whi)
{
    int blk = blockIdx.x, tid = threadIdx.x;
    const float* src;
    hf* dst;
    if (blk < 3072)      { src = qkv_w  + (long long)blk * 1024; dst = whi + W_QKV  + (long long)blk * 1024; }
    else if (blk < 4096) { src = proj_w + (long long)(blk - 3072) * 1024; dst = whi + W_PROJ + (long long)(blk - 3072) * 1024; }
    else if (blk < 5120) { int r = blk - 4096; src = kq_w + (long long)r * 1024; dst = whi + W_KQKV + (long long)r * 3072; }
    else if (blk < 6144) { int r = blk - 5120; src = kk_w + (long long)r * 1024; dst = whi + W_KQKV + (long long)r * 3072 + 1024; }
    else if (blk < 7168) { int r = blk - 6144; src = kv_w + (long long)r * 1024; dst = whi + W_KQKV + (long long)r * 3072 + 2048; }
    else if (blk < 8192) { src = ko_w  + (long long)(blk - 7168) * 1024; dst = whi + W_KO  + (long long)(blk - 7168) * 1024; }
    else if (blk < 12288){ src = fc1_w + (long long)(blk - 8192) * 1024; dst = whi + W_FC1 + (long long)(blk - 8192) * 1024; }
    else                 { src = fc2_w + (long long)(blk - 12288) * 1024; dst = whi + W_FC2 + (long long)(blk - 12288) * 1024; }
    float4 v = *(const float4*)(src + tid * 4);
    *(hf2*)(dst + tid * 4)     = __floats2half2_rn(v.x, v.y);
    *(hf2*)(dst + tid * 4 + 2) = __floats2half2_rn(v.z, v.w);
}

__global__ void __launch_bounds__(256) concat_bias(
    const float* __restrict__ a, const float* __restrict__ b,
    const float* __restrict__ c, float* __restrict__ o)
{
    int i = blockIdx.x * 256 + threadIdx.x;
    o[i] = (i < 1024) ? a[i] : ((i < 2048) ? b[i - 1024] : c[i - 2048]);
}

/* ---------------- theta + softmax -> fp16 (hi only) ----------------------- */
__global__ void __launch_bounds__(256) theta_softmax2048_hf(
    const float* __restrict__ S, hf* __restrict__ Phi)
{
    __shared__ float red[8];
    const float* row = S + (long long)blockIdx.x * 2048;
    long long ob = (long long)blockIdx.x * 2048;
    int tid = threadIdx.x;
    float4 v0 = ((const float4*)row)[tid];
    float4 v1 = ((const float4*)row)[tid + 256];
    v0.x = theta_fn(v0.x); v0.y = theta_fn(v0.y); v0.z = theta_fn(v0.z); v0.w = theta_fn(v0.w);
    v1.x = theta_fn(v1.x); v1.y = theta_fn(v1.y); v1.z = theta_fn(v1.z); v1.w = theta_fn(v1.w);
    float m = fmaxf(fmaxf(fmaxf(v0.x, v0.y), fmaxf(v0.z, v0.w)),
                    fmaxf(fmaxf(v1.x, v1.y), fmaxf(v1.z, v1.w)));
    #pragma unroll
    for (int o = 16; o; o >>= 1) m = fmaxf(m, __shfl_xor_sync(0xffffffffu, m, o));
    if ((tid & 31) == 0) red[tid >> 5] = m;
    __syncthreads();
    m = fmaxf(fmaxf(fmaxf(red[0], red[1]), fmaxf(red[2], red[3])),
              fmaxf(fmaxf(red[4], red[5]), fmaxf(red[6], red[7])));
    v0.x = __expf(v0.x - m); v0.y = __expf(v0.y - m); v0.z = __expf(v0.z - m); v0.w = __expf(v0.w - m);
    v1.x = __expf(v1.x - m); v1.y = __expf(v1.y - m); v1.z = __expf(v1.z - m); v1.w = __expf(v1.w - m);
    float s = v0.x + v0.y + v0.z + v0.w + v1.x + v1.y + v1.z + v1.w;
    #pragma unroll
    for (int o = 16; o; o >>= 1) s += __shfl_xor_sync(0xffffffffu, s, o);
    __syncthreads();
    if ((tid & 31) == 0) red[tid >> 5] = s;
    __syncthreads();
    s = red[0] + red[1] + red[2] + red[3] + red[4] + red[5] + red[6] + red[7];
    float r = 1.0f / s;
    v0.x *= r; v0.y *= r; v0.z *= r; v0.w *= r;
    v1.x *= r; v1.y *= r; v1.z *= r; v1.w *= r;
    *(hf2*)(Phi + ob + tid*4)            = __floats2half2_rn(v0.x, v0.y);
    *(hf2*)(Phi + ob + tid*4 + 2)        = __floats2half2_rn(v0.z, v0.w);
    *(hf2*)(Phi + ob + 1024 + tid*4)     = __floats2half2_rn(v1.x, v1.y);
    *(hf2*)(Phi + ob + 1024 + tid*4 + 2) = __floats2half2_rn(v1.z, v1.w);
}

/* ---------------- LayerNorm over 1024 -> fp16 ----------------------------- */
__global__ void __launch_bounds__(256) layernorm1024_hf(
    const float* __restrict__ X, const float* __restrict__ g,
    const float* __restrict__ bta, hf* __restrict__ Yhi)
{
    __shared__ float rs[8], rq[8];
    long long base = (long long)blockIdx.x * 1024;
    int tid = threadIdx.x;
    float4 v = *(const float4*)(X + base + tid * 4);
    float s = v.x + v.y + v.z + v.w;
    float q = v.x*v.x + v.y*v.y + v.z*v.z + v.w*v.w;
    #pragma unroll
    for (int o = 16; o; o >>= 1) {
        s += __shfl_xor_sync(0xffffffffu, s, o);
        q += __shfl_xor_sync(0xffffffffu, q, o);
    }
    if ((tid & 31) == 0) { rs[tid >> 5] = s; rq[tid >> 5] = q; }
    __syncthreads();
    s = rs[0] + rs[1] + rs[2] + rs[3] + rs[4] + rs[5] + rs[6] + rs[7];
    q = rq[0] + rq[1] + rq[2] + rq[3] + rq[4] + rq[5] + rq[6] + rq[7];
    float mu  = s * (1.0f / 1024.0f);
    float var = q * (1.0f / 1024.0f) - mu * mu;
    float inv = rsqrtf(var + 1e-5f);
    float4 gg = *(const float4*)(g + tid * 4);
    float4 bb = *(const float4*)(bta + tid * 4);
    float o0 = (v.x - mu) * inv * gg.x + bb.x;
    float o1 = (v.y - mu) * inv * gg.y + bb.y;
    float o2 = (v.z - mu) * inv * gg.z + bb.z;
    float o3 = (v.w - mu) * inv * gg.w + bb.w;
    *(hf2*)(Yhi + base + tid*4)     = __floats2half2_rn(o0, o1);
    *(hf2*)(Yhi + base + tid*4 + 2) = __floats2half2_rn(o2, o3);
}

/* ---------------- residual adds ------------------------------------------- */
__global__ void __launch_bounds__(256) add_hf(
    float* __restrict__ out, const float* __restrict__ a, const float* __restrict__ b,
    hf* __restrict__ hi)
{
    long long i = ((long long)blockIdx.x * 256 + threadIdx.x) * 4;
    float4 av = *(const float4*)(a + i);
    float4 bv = *(const float4*)(b + i);
    av.x += bv.x; av.y += bv.y; av.z += bv.z; av.w += bv.w;
    *(float4*)(out + i) = av;
    *(hf2*)(hi + i)     = __floats2half2_rn(av.x, av.y);
    *(hf2*)(hi + i + 2) = __floats2half2_rn(av.z, av.w);
}
__global__ void __launch_bounds__(256) add_plain(
    float* __restrict__ out, const float* __restrict__ b)
{
    long long i = ((long long)blockIdx.x * 256 + threadIdx.x) * 4;
    float4 av = *(const float4*)(out + i);
    float4 bv = *(const float4*)(b + i);
    av.x += bv.x; av.y += bv.y; av.z += bv.z; av.w += bv.w;
    *(float4*)(out + i) = av;
}

/* ---------------- host-side dispatch -------------------------------------- */
#define SMEM_G     99328    /* 3*(16384+16384) + 1024 ; 2 CTAs/SM */
#define SMEM_FLASH 107520   /* 8192 + 3*32768 + 1024 ; 2 CTAs/SM */

extern "C" void kernel_launch(void* const* d_in, const int* in_sizes, int n_in,
                              void* d_out, int out_size)
{
    const float* x     = (const float*)d_in[0];
    const float* ln1_g = (const float*)d_in[1];
    const float* ln1_b = (const float*)d_in[2];
    const float* qkv_w = (const float*)d_in[3];
    const float* qkv_b = (const float*)d_in[4];
    const float* proj_w= (const float*)d_in[5];
    const float* proj_b= (const float*)d_in[6];
    const float* kq_w  = (const float*)d_in[7];
    const float* kq_b  = (const float*)d_in[8];
    const float* kk_w  = (const float*)d_in[9];
    const float* kk_b  = (const float*)d_in[10];
    const float* kv_w  = (const float*)d_in[11];
    const float* kv_b  = (const float*)d_in[12];
    const float* ko_w  = (const float*)d_in[13];
    const float* ko_b  = (const float*)d_in[14];
    const float* ln2_g = (const float*)d_in[15];
    const float* ln2_b = (const float*)d_in[16];
    const float* fc1_w = (const float*)d_in[17];
    const float* fc1_b = (const float*)d_in[18];
    const float* fc2_w = (const float*)d_in[19];
    const float* fc2_b = (const float*)d_in[20];
    float* out = (float*)d_out;

    float *sc, *bufA, *bias3;
    hf *whi, *lnhi, *qkvhi, *schi, *aohi, *reshi, *ffhi;
    cudaGetSymbolAddress((void**)&sc,    g_sc);
    cudaGetSymbolAddress((void**)&bufA,  g_bufA);
    cudaGetSymbolAddress((void**)&bias3, g_bias3);
    cudaGetSymbolAddress((void**)&whi,   g_whi);
    cudaGetSymbolAddress((void**)&lnhi,  g_lnhi);
    cudaGetSymbolAddress((void**)&qkvhi, g_qkvhi);
    cudaGetSymbolAddress((void**)&schi,  g_schi);
    cudaGetSymbolAddress((void**)&aohi,  g_aohi);
    cudaGetSymbolAddress((void**)&reshi, g_reshi);
    cudaGetSymbolAddress((void**)&ffhi,  g_ffhi);

    cudaFuncSetAttribute(bgemm<128, false, false, 1>, cudaFuncAttributeMaxDynamicSharedMemorySize, SMEM_G);
    cudaFuncSetAttribute(bgemm<128, false, false, 0>, cudaFuncAttributeMaxDynamicSharedMemorySize, SMEM_G);
    cudaFuncSetAttribute(bgemm<128, false, true,  1>, cudaFuncAttributeMaxDynamicSharedMemorySize, SMEM_G);
    cudaFuncSetAttribute(bgemm<128, true,  false, 0>, cudaFuncAttributeMaxDynamicSharedMemorySize, SMEM_G);
    cudaFuncSetAttribute(flash_mha, cudaFuncAttributeMaxDynamicSharedMemorySize, SMEM_FLASH);

    const long long NN = (long long)NTOK * NTOK;
    const long long TC = (long long)NTOK * DIMC;
    const int nElemBlks = (TTOK * DIMC) / (4 * 256);
    dim3 tb(256);

    conv_all<<<16384, tb>>>(qkv_w, proj_w, kq_w, kk_w, kv_w, ko_w, fc1_w, fc2_w, whi);
    concat_bias<<<12, tb>>>(kq_b, kk_b, kv_b, bias3);
    layernorm1024_hf<<<TTOK, tb>>>(x, ln1_g, ln1_b, lnhi);

    /* qkv = ln1 @ qkv_w + b */
    bgemm<128, false, false, 1><<<dim3(24, 32, 1), tb, SMEM_G>>>(
        lnhi, whi + W_QKV, nullptr, qkvhi, qkv_b,
        1024, 1024, 3072, 3072, 1, 0,0, 0,0, 0,0, 1.0f);

    /* fused MHA attention -> aohi (q-tile 64, 2 CTAs/SM) */
    flash_mha<<<dim3(32, 32), tb, SMEM_FLASH>>>(qkvhi, aohi);

    bgemm<128, false, false, 0><<<dim3(8, 32, 1), tb, SMEM_G>>>(
        aohi, whi + W_PROJ, bufA, nullptr, proj_b,
        1024, 1024, 1024, 1024, 1, 0,0, 0,0, 0,0, 1.0f);
    add_hf<<<nElemBlks, tb>>>(out, x, bufA, reshi);

    /* ---- sublayer 2: kernel attention ---- */
    bgemm<128, false, false, 1><<<dim3(24, 32, 1), tb, SMEM_G>>>(
        reshi, whi + W_KQKV, nullptr, qkvhi, bias3,
        1024, 1024, 3072, 3072, 1, 0,0, 0,0, 0,0, 1.0f);

    hf* bqhi = qkvhi;
    hf* bkhi = qkvhi + DIMC;
    hf* bvhi = qkvhi + 2 * DIMC;

    bgemm<128, true, false, 0><<<dim3(16, 16, BATCHN), tb, SMEM_G>>>(
        bqhi, bkhi, sc, nullptr, nullptr,
        1024, 3072, 3072, NTOK, 1,
        (long long)NTOK*3*DIMC, 0, (long long)NTOK*3*DIMC, 0, NN, 0, 1.0f);

    theta_softmax2048_hf<<<BATCHN*NTOK, tb>>>(sc, schi);

    bgemm<128, false, false, 1><<<dim3(8, 16, BATCHN), tb, SMEM_G>>>(
        schi, bvhi, nullptr, aohi, nullptr,
        NTOK, NTOK, 3*DIMC, DIMC, 1,
        NN, 0, (long long)NTOK*3*DIMC, 0, TC, 0, 1.0f);

    bgemm<128, false, false, 0><<<dim3(8, 32, 1), tb, SMEM_G>>>(
        aohi, whi + W_KO, bufA, nullptr, ko_b,
        1024, 1024, 1024, 1024, 1, 0,0, 0,0, 0,0, 1.0f);
    add_plain<<<nElemBlks, tb>>>(out, bufA);

    /* ---- sublayer 3: FFN ---- */
    layernorm1024_hf<<<TTOK, tb>>>(out, ln2_g, ln2_b, lnhi);
    bgemm<128, false, true, 1><<<dim3(32, 32, 1), tb, SMEM_G>>>(
        lnhi, whi + W_FC1, nullptr, ffhi, fc1_b,
        1024, 1024, 4096, 4096, 1, 0,0, 0,0, 0,0, 1.0f);
    bgemm<128, false, false, 0><<<dim3(8, 32, 1), tb, SMEM_G>>>(
        ffhi, whi + W_FC2, bufA, nullptr, fc2_b,
        4096, 4096, 1024, 1024, 1, 0,0, 0,0, 0,0, 1.0f);
    add_plain<<<nElemBlks, tb>>>(out, bufA);
}